// round 2
// baseline (speedup 1.0000x reference)
#include <cuda_runtime.h>
#include <cstdint>
#include <cstddef>

// Problem constants (fixed by the dataset)
#define M_NODES 100000
#define N_EDG   1600000

// If the bench's JAX uses the legacy (non-partitionable) threefry path, set to 0.
#define JAX_PARTITIONABLE 1

// ---------------- scratch (static device globals; no allocation) ----------------
__device__ int   g_deg[M_NODES];
__device__ float g_dis[M_NODES];
__device__ float g_norm[N_EDG];
__device__ __align__(16) float g_bufA[(size_t)M_NODES * 128];
__device__ __align__(16) float g_bufB[(size_t)M_NODES * 128];
__device__ __align__(16) float g_bufO[(size_t)M_NODES * 128];
__device__ __align__(16) float g_bufC[(size_t)M_NODES * 128];

// ---------------- threefry2x32 (shared host/device) ----------------
__host__ __device__ __forceinline__ unsigned tf_rotl(unsigned x, int r) {
  return (x << r) | (x >> (32 - r));
}

__host__ __device__ __forceinline__ void threefry2x32(
    unsigned k0, unsigned k1, unsigned x0, unsigned x1,
    unsigned& o0, unsigned& o1) {
  unsigned ks2 = k0 ^ k1 ^ 0x1BD11BDAu;
  x0 += k0; x1 += k1;
#define TF_R(r) { x0 += x1; x1 = tf_rotl(x1, (r)); x1 ^= x0; }
  TF_R(13) TF_R(15) TF_R(26) TF_R(6)
  x0 += k1;  x1 += ks2 + 1u;
  TF_R(17) TF_R(29) TF_R(16) TF_R(24)
  x0 += ks2; x1 += k0 + 2u;
  TF_R(13) TF_R(15) TF_R(26) TF_R(6)
  x0 += k0;  x1 += k1 + 3u;
  TF_R(17) TF_R(29) TF_R(16) TF_R(24)
  x0 += k1;  x1 += ks2 + 4u;
  TF_R(13) TF_R(15) TF_R(26) TF_R(6)
  x0 += ks2; x1 += k0 + 5u;
#undef TF_R
  o0 = x0; o1 = x1;
}

// ---------------- small utility kernels ----------------
__global__ void k_zero_f(float* p, int n) {
  int i = blockIdx.x * blockDim.x + threadIdx.x;
  if (i < n) p[i] = 0.0f;
}

__global__ void k_zero_i(int* p, int n) {
  int i = blockIdx.x * blockDim.x + threadIdx.x;
  if (i < n) p[i] = 0;
}

__global__ void k_deg(const int* __restrict__ ei, int* __restrict__ deg) {
  int e = blockIdx.x * blockDim.x + threadIdx.x;
  if (e >= N_EDG) return;
  int col = ei[N_EDG + e];
  if ((unsigned)col < (unsigned)M_NODES) atomicAdd(&deg[col], 1);
}

__global__ void k_dis(const int* __restrict__ deg, float* __restrict__ dis) {
  int i = blockIdx.x * blockDim.x + threadIdx.x;
  if (i >= M_NODES) return;
  int d = deg[i];
  dis[i] = (d > 0) ? rsqrtf((float)d) : 0.0f;
}

__global__ void k_norm(const int* __restrict__ ei,
                       const float* __restrict__ dis,
                       float* __restrict__ norm) {
  int e = blockIdx.x * blockDim.x + threadIdx.x;
  if (e >= N_EDG) return;
  int row = ei[e];
  int col = ei[N_EDG + e];
  float v = 0.0f;
  if ((unsigned)row < (unsigned)M_NODES && (unsigned)col < (unsigned)M_NODES)
    v = dis[row] * dis[col];
  norm[e] = v;
}

// ---------------- SpMM hop: out[col] += norm_e * h[row], per edge ----------------
// One thread per (edge, 4-dim chunk). Consecutive threads = consecutive chunks of
// one edge -> coalesced gather; scatter via vectorized red.global.add.v4.
template <int D>
__global__ void k_spmm(float* __restrict__ out, const float* __restrict__ h,
                       const int* __restrict__ ei,
                       const float* __restrict__ norm) {
  constexpr int CH = D / 4;
  long long tid = (long long)blockIdx.x * blockDim.x + threadIdx.x;
  if (tid >= (long long)N_EDG * CH) return;
  int c = (int)(tid % CH);
  int e = (int)(tid / CH);
  int row = __ldg(&ei[e]);
  int col = __ldg(&ei[N_EDG + e]);
  if ((unsigned)row >= (unsigned)M_NODES || (unsigned)col >= (unsigned)M_NODES) return;
  float nm = __ldg(&norm[e]);
  const float4 v = *(const float4*)(h + (size_t)row * D + c * 4);
  float4 r;
  r.x = v.x * nm; r.y = v.y * nm; r.z = v.z * nm; r.w = v.w * nm;
  float* dst = out + (size_t)col * D + c * 4;
  asm volatile("red.global.add.v4.f32 [%0], {%1, %2, %3, %4};"
               :: "l"(dst), "f"(r.x), "f"(r.y), "f"(r.z), "f"(r.w)
               : "memory");
}

// ---------------- bias broadcast ----------------
__global__ void k_bias(float* __restrict__ out, const float* __restrict__ b, int n, int N) {
  int i = blockIdx.x * blockDim.x + threadIdx.x;
  if (i < n) out[i] = b[i % N];
}

// ---------------- accumulate GEMM: out[M,N] += in[M,K] @ W[N,K]^T ----------------
// Block = N*8 threads, 32 rows per block (each thread: 4 rows x 1 col).
// Requires M % 32 == 0 (100000 = 3125 * 32).
template <int N, int K>
__global__ void k_gemm_acc(float* __restrict__ out, const float* __restrict__ in,
                           const float* __restrict__ W) {
  constexpr int BM = 32, BK = 32, NT = N * 8;
  __shared__ float sIn[BM][BK];
  __shared__ float sW[N][BK + 1];
  int tid = threadIdx.x;
  int n = tid % N;
  int mg = tid / N;           // 0..7
  int m0 = blockIdx.x * BM;
  float acc[4] = {0.f, 0.f, 0.f, 0.f};
  for (int t = 0; t < K; t += BK) {
    for (int i = tid; i < BM * BK; i += NT) {
      int m = i / BK, k = i % BK;
      sIn[m][k] = in[(size_t)(m0 + m) * K + t + k];
    }
    for (int i = tid; i < N * BK; i += NT) {
      int nn = i / BK, k = i % BK;
      sW[nn][k] = W[(size_t)nn * K + t + k];
    }
    __syncthreads();
#pragma unroll
    for (int k = 0; k < BK; k++) {
      float w = sW[n][k];
#pragma unroll
      for (int i = 0; i < 4; i++) acc[i] += sIn[mg * 4 + i][k] * w;
    }
    __syncthreads();
  }
#pragma unroll
  for (int i = 0; i < 4; i++) {
    int m = m0 + mg * 4 + i;
    out[(size_t)m * N + n] += acc[i];
  }
}

// ---------------- activations / dropout ----------------
__global__ void k_elu(float* p, int n) {
  int i = blockIdx.x * blockDim.x + threadIdx.x;
  if (i >= n) return;
  float v = p[i];
  p[i] = (v > 0.0f) ? v : expm1f(v);
}

#if JAX_PARTITIONABLE
// bits(i) = x0 ^ x1 of threefry(key, hi(i)=0, lo(i)=i);  u = bits>>9 | 1.0f - 1;  keep = u < 0.5
__global__ void k_dropout(float* p, int n, unsigned k0, unsigned k1) {
  int i = blockIdx.x * blockDim.x + threadIdx.x;
  if (i >= n) return;
  unsigned o0, o1;
  threefry2x32(k0, k1, 0u, (unsigned)i, o0, o1);
  unsigned bits = o0 ^ o1;
  float u = __uint_as_float((bits >> 9) | 0x3F800000u) - 1.0f;
  p[i] = (u < 0.5f) ? p[i] * 2.0f : 0.0f;
}
#else
// Legacy path: counts = iota(n); pairs (j, j+n/2); bits[j]=x0, bits[j+n/2]=x1.
__global__ void k_dropout(float* p, int n, unsigned k0, unsigned k1) {
  int j = blockIdx.x * blockDim.x + threadIdx.x;
  int half = n / 2;
  if (j >= half) return;
  unsigned o0, o1;
  threefry2x32(k0, k1, (unsigned)j, (unsigned)(j + half), o0, o1);
  float u0 = __uint_as_float((o0 >> 9) | 0x3F800000u) - 1.0f;
  float u1 = __uint_as_float((o1 >> 9) | 0x3F800000u) - 1.0f;
  p[j]        = (u0 < 0.5f) ? p[j] * 2.0f        : 0.0f;
  p[j + half] = (u1 < 0.5f) ? p[j + half] * 2.0f : 0.0f;
}
#endif

// ---------------- host orchestration ----------------
static inline int cdiv(long long a, int b) { return (int)((a + b - 1) / b); }

extern "C" void kernel_launch(void* const* d_in, const int* in_sizes, int n_in,
                              void* d_out, int out_size) {
  const float* x  = (const float*)d_in[0];
  const int*   ei = (const int*)d_in[1];   // int32: JAX x64 disabled downcasts int64
  const float* W1 = (const float*)d_in[2];
  const float* b1 = (const float*)d_in[3];
  const float* W2 = (const float*)d_in[4];
  const float* b2 = (const float*)d_in[5];
  const float* W3 = (const float*)d_in[6];
  const float* b3 = (const float*)d_in[7];
  float* out = (float*)d_out;

  int*   deg;  float *dis, *norm, *bufA, *bufB, *bufO, *bufC;
  cudaGetSymbolAddress((void**)&deg,  g_deg);
  cudaGetSymbolAddress((void**)&dis,  g_dis);
  cudaGetSymbolAddress((void**)&norm, g_norm);
  cudaGetSymbolAddress((void**)&bufA, g_bufA);
  cudaGetSymbolAddress((void**)&bufB, g_bufB);
  cudaGetSymbolAddress((void**)&bufO, g_bufO);
  cudaGetSymbolAddress((void**)&bufC, g_bufC);

  // dropout keys: dk1, dk2 = split(key(42))
  unsigned dk1a, dk1b, dk2a, dk2b;
#if JAX_PARTITIONABLE
  threefry2x32(0u, 42u, 0u, 0u, dk1a, dk1b);
  threefry2x32(0u, 42u, 0u, 1u, dk2a, dk2b);
#else
  unsigned a0, a1, c0, c1;
  threefry2x32(0u, 42u, 0u, 2u, a0, c0);
  threefry2x32(0u, 42u, 1u, 3u, a1, c1);
  dk1a = a0; dk1b = a1; dk2a = c0; dk2b = c1;
#endif

  const int T = 256;

  // ---- degree / norm ----
  k_zero_i<<<cdiv(M_NODES, T), T>>>(deg, M_NODES);
  k_deg  <<<cdiv(N_EDG,   T), T>>>(ei, deg);
  k_dis  <<<cdiv(M_NODES, T), T>>>(deg, dis);
  k_norm <<<cdiv(N_EDG,   T), T>>>(ei, dis, norm);

  // ---- layer 1: 128 -> 128 ----
  {
    const int D = 128, N = 128;
    k_bias<<<cdiv((long long)M_NODES * N, T), T>>>(bufO, b1, M_NODES * N, N);
    k_gemm_acc<128, 128><<<M_NODES / 32, 128 * 8>>>(bufO, x, W1);
    const float* hc = x;
    float* hn = bufA;
    for (int k = 1; k <= 3; k++) {
      k_zero_f<<<cdiv((long long)M_NODES * D, T), T>>>(hn, M_NODES * D);
      k_spmm<128><<<cdiv((long long)N_EDG * (D / 4), T), T>>>(hn, hc, ei, norm);
      k_gemm_acc<128, 128><<<M_NODES / 32, 128 * 8>>>(bufO, hn, W1 + (size_t)k * 128 * 128);
      hc = hn;
      hn = (hn == bufA) ? bufB : bufA;
    }
    k_dropout<<<cdiv((long long)M_NODES * N, T), T>>>(bufO, M_NODES * N, dk1a, dk1b);
  }

  // ---- layer 2: 128 -> 64 ----
  {
    const int D = 128, N = 64;
    k_bias<<<cdiv((long long)M_NODES * N, T), T>>>(bufC, b2, M_NODES * N, N);
    k_gemm_acc<64, 128><<<M_NODES / 32, 64 * 8>>>(bufC, bufO, W2);
    const float* hc = bufO;
    float* hn = bufA;
    for (int k = 1; k <= 3; k++) {
      k_zero_f<<<cdiv((long long)M_NODES * D, T), T>>>(hn, M_NODES * D);
      k_spmm<128><<<cdiv((long long)N_EDG * (D / 4), T), T>>>(hn, hc, ei, norm);
      k_gemm_acc<64, 128><<<M_NODES / 32, 64 * 8>>>(bufC, hn, W2 + (size_t)k * 64 * 128);
      hc = hn;
      hn = (hn == bufA) ? bufB : bufA;
    }
    k_elu<<<cdiv((long long)M_NODES * N, T), T>>>(bufC, M_NODES * N);
    k_dropout<<<cdiv((long long)M_NODES * N, T), T>>>(bufC, M_NODES * N, dk2a, dk2b);
  }

  // ---- layer 3: 64 -> 16 (writes d_out) ----
  {
    const int D = 64, N = 16;
    k_bias<<<cdiv((long long)M_NODES * N, T), T>>>(out, b3, M_NODES * N, N);
    k_gemm_acc<16, 64><<<M_NODES / 32, 16 * 8>>>(out, bufC, W3);
    const float* hc = bufC;
    float* hn = bufA;
    for (int k = 1; k <= 3; k++) {
      k_zero_f<<<cdiv((long long)M_NODES * D, T), T>>>(hn, M_NODES * D);
      k_spmm<64><<<cdiv((long long)N_EDG * (D / 4), T), T>>>(hn, hc, ei, norm);
      k_gemm_acc<16, 64><<<M_NODES / 32, 16 * 8>>>(out, hn, W3 + (size_t)k * 16 * 64);
      hc = hn;
      hn = (hn == bufA) ? bufB : bufA;
    }
  }
}

// round 3
// speedup vs baseline: 1.3590x; 1.3590x over previous
#include <cuda_runtime.h>
#include <cstdint>
#include <cstddef>

#define M_NODES 100000
#define N_EDG   1600000
#define JAX_PARTITIONABLE 1

// ---------------- scratch (static device globals; no allocation) ----------------
__device__ int   g_deg[M_NODES];
__device__ float g_dis[M_NODES];
__device__ float g_norm[N_EDG];
__device__ __align__(16) float g_bufA[(size_t)M_NODES * 128];
__device__ __align__(16) float g_bufB[(size_t)M_NODES * 128];
__device__ __align__(16) float g_bufC[(size_t)M_NODES * 128];
__device__ __align__(16) float g_bufD[(size_t)M_NODES * 128];
__device__ __align__(16) float g_bufE[(size_t)M_NODES * 128];

// ---------------- threefry2x32 ----------------
__host__ __device__ __forceinline__ unsigned tf_rotl(unsigned x, int r) {
  return (x << r) | (x >> (32 - r));
}

__host__ __device__ __forceinline__ void threefry2x32(
    unsigned k0, unsigned k1, unsigned x0, unsigned x1,
    unsigned& o0, unsigned& o1) {
  unsigned ks2 = k0 ^ k1 ^ 0x1BD11BDAu;
  x0 += k0; x1 += k1;
#define TF_R(r) { x0 += x1; x1 = tf_rotl(x1, (r)); x1 ^= x0; }
  TF_R(13) TF_R(15) TF_R(26) TF_R(6)
  x0 += k1;  x1 += ks2 + 1u;
  TF_R(17) TF_R(29) TF_R(16) TF_R(24)
  x0 += ks2; x1 += k0 + 2u;
  TF_R(13) TF_R(15) TF_R(26) TF_R(6)
  x0 += k0;  x1 += k1 + 3u;
  TF_R(17) TF_R(29) TF_R(16) TF_R(24)
  x0 += k1;  x1 += ks2 + 4u;
  TF_R(13) TF_R(15) TF_R(26) TF_R(6)
  x0 += ks2; x1 += k0 + 5u;
#undef TF_R
  o0 = x0; o1 = x1;
}

// ---------------- norm pipeline ----------------
__global__ void k_zero_i(int* p, int n) {
  int i = blockIdx.x * blockDim.x + threadIdx.x;
  if (i < n) p[i] = 0;
}

__global__ void k_deg(const int* __restrict__ ei, int* __restrict__ deg) {
  int e = blockIdx.x * blockDim.x + threadIdx.x;
  if (e >= N_EDG) return;
  int col = ei[N_EDG + e];
  if ((unsigned)col < (unsigned)M_NODES) atomicAdd(&deg[col], 1);
}

__global__ void k_dis(const int* __restrict__ deg, float* __restrict__ dis) {
  int i = blockIdx.x * blockDim.x + threadIdx.x;
  if (i >= M_NODES) return;
  int d = deg[i];
  dis[i] = (d > 0) ? rsqrtf((float)d) : 0.0f;
}

__global__ void k_norm(const int* __restrict__ ei,
                       const float* __restrict__ dis,
                       float* __restrict__ norm) {
  int e = blockIdx.x * blockDim.x + threadIdx.x;
  if (e >= N_EDG) return;
  int row = ei[e];
  int col = ei[N_EDG + e];
  float v = 0.0f;
  if ((unsigned)row < (unsigned)M_NODES && (unsigned)col < (unsigned)M_NODES)
    v = dis[row] * dis[col];
  norm[e] = v;
}

// ---------------- SpMM hop: out[col] += norm_e * h[row] (out pre-seeded) ----------------
template <int D>
__global__ void k_spmm(float* __restrict__ out, const float* __restrict__ h,
                       const int* __restrict__ ei,
                       const float* __restrict__ norm) {
  constexpr int CH = D / 4;
  long long tid = (long long)blockIdx.x * blockDim.x + threadIdx.x;
  if (tid >= (long long)N_EDG * CH) return;
  int c = (int)(tid % CH);
  int e = (int)(tid / CH);
  int row = __ldg(&ei[e]);
  int col = __ldg(&ei[N_EDG + e]);
  if ((unsigned)row >= (unsigned)M_NODES || (unsigned)col >= (unsigned)M_NODES) return;
  float nm = __ldg(&norm[e]);
  const float4 v = *(const float4*)(h + (size_t)row * D + c * 4);
  float4 r;
  r.x = v.x * nm; r.y = v.y * nm; r.z = v.z * nm; r.w = v.w * nm;
  float* dst = out + (size_t)col * D + c * 4;
  asm volatile("red.global.add.v4.f32 [%0], {%1, %2, %3, %4};"
               :: "l"(dst), "f"(r.x), "f"(r.y), "f"(r.z), "f"(r.w)
               : "memory");
}

// ---------------- GEMM (write mode): out[M,N] = in[M,K] @ W[N,K]^T (+ b) ----------------
// Block = N*8 threads, 32 rows/block; each thread: 4 rows x 1 col. M % 32 == 0.
template <int N, int K, bool BIAS>
__global__ void k_gemm(float* __restrict__ out, const float* __restrict__ in,
                       const float* __restrict__ W, const float* __restrict__ b) {
  constexpr int BM = 32, BK = 32, NT = N * 8;
  __shared__ float sIn[BM][BK];
  __shared__ float sW[N][BK + 1];
  int tid = threadIdx.x;
  int n = tid % N;
  int mg = tid / N;           // 0..7
  int m0 = blockIdx.x * BM;
  float acc[4] = {0.f, 0.f, 0.f, 0.f};
  for (int t = 0; t < K; t += BK) {
    for (int i = tid; i < BM * BK; i += NT) {
      int m = i / BK, k = i % BK;
      sIn[m][k] = in[(size_t)(m0 + m) * K + t + k];
    }
    for (int i = tid; i < N * BK; i += NT) {
      int nn = i / BK, k = i % BK;
      sW[nn][k] = W[(size_t)nn * K + t + k];
    }
    __syncthreads();
#pragma unroll
    for (int k = 0; k < BK; k++) {
      float w = sW[n][k];
#pragma unroll
      for (int i = 0; i < 4; i++) acc[i] += sIn[mg * 4 + i][k] * w;
    }
    __syncthreads();
  }
  float bb = BIAS ? b[n] : 0.0f;
#pragma unroll
  for (int i = 0; i < 4; i++) {
    int m = m0 + mg * 4 + i;
    out[(size_t)m * N + n] = acc[i] + bb;
  }
}

// ---------------- dropout (+ optional ELU first) ----------------
#if JAX_PARTITIONABLE
template <bool ELU>
__global__ void k_dropout(float* p, int n, unsigned k0, unsigned k1) {
  int i = blockIdx.x * blockDim.x + threadIdx.x;
  if (i >= n) return;
  unsigned o0, o1;
  threefry2x32(k0, k1, 0u, (unsigned)i, o0, o1);
  unsigned bits = o0 ^ o1;
  float u = __uint_as_float((bits >> 9) | 0x3F800000u) - 1.0f;
  float v = p[i];
  if (ELU) v = (v > 0.0f) ? v : expm1f(v);
  p[i] = (u < 0.5f) ? v * 2.0f : 0.0f;
}
#else
template <bool ELU>
__global__ void k_dropout(float* p, int n, unsigned k0, unsigned k1) {
  int j = blockIdx.x * blockDim.x + threadIdx.x;
  int half = n / 2;
  if (j >= half) return;
  unsigned o0, o1;
  threefry2x32(k0, k1, (unsigned)j, (unsigned)(j + half), o0, o1);
  float u0 = __uint_as_float((o0 >> 9) | 0x3F800000u) - 1.0f;
  float u1 = __uint_as_float((o1 >> 9) | 0x3F800000u) - 1.0f;
  float v0 = p[j], v1 = p[j + half];
  if (ELU) {
    v0 = (v0 > 0.0f) ? v0 : expm1f(v0);
    v1 = (v1 > 0.0f) ? v1 : expm1f(v1);
  }
  p[j]        = (u0 < 0.5f) ? v0 * 2.0f : 0.0f;
  p[j + half] = (u1 < 0.5f) ? v1 * 2.0f : 0.0f;
}
#endif

// ---------------- host orchestration ----------------
static inline int cdiv(long long a, int b) { return (int)((a + b - 1) / b); }

extern "C" void kernel_launch(void* const* d_in, const int* in_sizes, int n_in,
                              void* d_out, int out_size) {
  const float* x  = (const float*)d_in[0];
  const int*   ei = (const int*)d_in[1];   // int32 (JAX x64 disabled)
  const float* W1 = (const float*)d_in[2];
  const float* b1 = (const float*)d_in[3];
  const float* W2 = (const float*)d_in[4];
  const float* b2 = (const float*)d_in[5];
  const float* W3 = (const float*)d_in[6];
  const float* b3 = (const float*)d_in[7];
  float* out = (float*)d_out;

  int* deg; float *dis, *norm, *bA, *bB, *bC, *bD, *bE;
  cudaGetSymbolAddress((void**)&deg,  g_deg);
  cudaGetSymbolAddress((void**)&dis,  g_dis);
  cudaGetSymbolAddress((void**)&norm, g_norm);
  cudaGetSymbolAddress((void**)&bA,   g_bufA);
  cudaGetSymbolAddress((void**)&bB,   g_bufB);
  cudaGetSymbolAddress((void**)&bC,   g_bufC);
  cudaGetSymbolAddress((void**)&bD,   g_bufD);
  cudaGetSymbolAddress((void**)&bE,   g_bufE);

  unsigned dk1a, dk1b, dk2a, dk2b;
#if JAX_PARTITIONABLE
  threefry2x32(0u, 42u, 0u, 0u, dk1a, dk1b);
  threefry2x32(0u, 42u, 0u, 1u, dk2a, dk2b);
#else
  unsigned a0, a1, c0, c1;
  threefry2x32(0u, 42u, 0u, 2u, a0, c0);
  threefry2x32(0u, 42u, 1u, 3u, a1, c1);
  dk1a = a0; dk1b = a1; dk2a = c0; dk2b = c1;
#endif

  const int T = 256;

  // ---- degree / norm ----
  k_zero_i<<<cdiv(M_NODES, T), T>>>(deg, M_NODES);
  k_deg  <<<cdiv(N_EDG,   T), T>>>(ei, deg);
  k_dis  <<<cdiv(M_NODES, T), T>>>(deg, dis);
  k_norm <<<cdiv(N_EDG,   T), T>>>(ei, dis, norm);

  // Horner per layer: P_k = h @ W_k^T; t = P3; P2 += A t; P1 += A P2; P0 += A P1.
  // A commutes with the feature-space linear maps, so hops run at OUTPUT width.

  // ---- layer 1: 128 -> 128.  planes: A(P0+bias), B(P1), C(P2), D(P3). h = x ----
  {
    const int N = 128, K = 128;
    k_gemm<N, K, true ><<<M_NODES / 32, N * 8>>>(bA, x, W1 + 0 * N * K, b1);
    k_gemm<N, K, false><<<M_NODES / 32, N * 8>>>(bB, x, W1 + 1 * N * K, nullptr);
    k_gemm<N, K, false><<<M_NODES / 32, N * 8>>>(bC, x, W1 + 2 * N * K, nullptr);
    k_gemm<N, K, false><<<M_NODES / 32, N * 8>>>(bD, x, W1 + 3 * N * K, nullptr);
    k_spmm<N><<<cdiv((long long)N_EDG * (N / 4), T), T>>>(bC, bD, ei, norm);
    k_spmm<N><<<cdiv((long long)N_EDG * (N / 4), T), T>>>(bB, bC, ei, norm);
    k_spmm<N><<<cdiv((long long)N_EDG * (N / 4), T), T>>>(bA, bB, ei, norm);
    k_dropout<false><<<cdiv((long long)M_NODES * N, T), T>>>(bA, M_NODES * N, dk1a, dk1b);
  }

  // ---- layer 2: 128 -> 64.  h = bA. planes: B(P0+bias), C, D, E ----
  {
    const int N = 64, K = 128;
    k_gemm<N, K, true ><<<M_NODES / 32, N * 8>>>(bB, bA, W2 + 0 * N * K, b2);
    k_gemm<N, K, false><<<M_NODES / 32, N * 8>>>(bC, bA, W2 + 1 * N * K, nullptr);
    k_gemm<N, K, false><<<M_NODES / 32, N * 8>>>(bD, bA, W2 + 2 * N * K, nullptr);
    k_gemm<N, K, false><<<M_NODES / 32, N * 8>>>(bE, bA, W2 + 3 * N * K, nullptr);
    k_spmm<N><<<cdiv((long long)N_EDG * (N / 4), T), T>>>(bD, bE, ei, norm);
    k_spmm<N><<<cdiv((long long)N_EDG * (N / 4), T), T>>>(bC, bD, ei, norm);
    k_spmm<N><<<cdiv((long long)N_EDG * (N / 4), T), T>>>(bB, bC, ei, norm);
    k_dropout<true><<<cdiv((long long)M_NODES * N, T), T>>>(bB, M_NODES * N, dk2a, dk2b);
  }

  // ---- layer 3: 64 -> 16.  h = bB. planes: out(P0+bias), C, D, E ----
  {
    const int N = 16, K = 64;
    k_gemm<N, K, true ><<<M_NODES / 32, N * 8>>>(out, bB, W3 + 0 * N * K, b3);
    k_gemm<N, K, false><<<M_NODES / 32, N * 8>>>(bC,  bB, W3 + 1 * N * K, nullptr);
    k_gemm<N, K, false><<<M_NODES / 32, N * 8>>>(bD,  bB, W3 + 2 * N * K, nullptr);
    k_gemm<N, K, false><<<M_NODES / 32, N * 8>>>(bE,  bB, W3 + 3 * N * K, nullptr);
    k_spmm<N><<<cdiv((long long)N_EDG * (N / 4), T), T>>>(bD,  bE, ei, norm);
    k_spmm<N><<<cdiv((long long)N_EDG * (N / 4), T), T>>>(bC,  bD, ei, norm);
    k_spmm<N><<<cdiv((long long)N_EDG * (N / 4), T), T>>>(out, bC, ei, norm);
  }
}

// round 4
// speedup vs baseline: 1.9178x; 1.4112x over previous
#include <cuda_runtime.h>
#include <cstdint>
#include <cstddef>

#define M_NODES 100000
#define N_EDG   1600000
#define JAX_PARTITIONABLE 1

// ---------------- scratch (static device globals; no allocation) ----------------
__device__ int   g_deg[M_NODES];
__device__ float g_dis[M_NODES];
__device__ float g_norm[N_EDG];
__device__ __align__(16) float g_bufA[(size_t)M_NODES * 128];
__device__ __align__(16) float g_bufB[(size_t)M_NODES * 128];
__device__ __align__(16) float g_bufC[(size_t)M_NODES * 128];
__device__ __align__(16) float g_bufD[(size_t)M_NODES * 128];
__device__ __align__(16) float g_bufE[(size_t)M_NODES * 128];

// ---------------- threefry2x32 ----------------
__host__ __device__ __forceinline__ unsigned tf_rotl(unsigned x, int r) {
  return (x << r) | (x >> (32 - r));
}

__host__ __device__ __forceinline__ void threefry2x32(
    unsigned k0, unsigned k1, unsigned x0, unsigned x1,
    unsigned& o0, unsigned& o1) {
  unsigned ks2 = k0 ^ k1 ^ 0x1BD11BDAu;
  x0 += k0; x1 += k1;
#define TF_R(r) { x0 += x1; x1 = tf_rotl(x1, (r)); x1 ^= x0; }
  TF_R(13) TF_R(15) TF_R(26) TF_R(6)
  x0 += k1;  x1 += ks2 + 1u;
  TF_R(17) TF_R(29) TF_R(16) TF_R(24)
  x0 += ks2; x1 += k0 + 2u;
  TF_R(13) TF_R(15) TF_R(26) TF_R(6)
  x0 += k0;  x1 += k1 + 3u;
  TF_R(17) TF_R(29) TF_R(16) TF_R(24)
  x0 += k1;  x1 += ks2 + 4u;
  TF_R(13) TF_R(15) TF_R(26) TF_R(6)
  x0 += ks2; x1 += k0 + 5u;
#undef TF_R
  o0 = x0; o1 = x1;
}

// ---------------- f32x2 packed helpers (Blackwell; ptxas won't auto-fuse) --------
__device__ __forceinline__ unsigned long long pack2(float a) {
  unsigned long long r;
  asm("mov.b64 %0, {%1, %1};" : "=l"(r) : "r"(__float_as_uint(a)));
  return r;
}
__device__ __forceinline__ unsigned long long ffma2(
    unsigned long long a, unsigned long long b, unsigned long long c) {
  unsigned long long d;
  asm("fma.rn.f32x2 %0, %1, %2, %3;" : "=l"(d) : "l"(a), "l"(b), "l"(c));
  return d;
}

// ---------------- norm pipeline ----------------
__global__ void k_zero_i(int* p, int n) {
  int i = blockIdx.x * blockDim.x + threadIdx.x;
  if (i < n) p[i] = 0;
}

__global__ void k_deg(const int* __restrict__ ei, int* __restrict__ deg) {
  int e = blockIdx.x * blockDim.x + threadIdx.x;
  if (e >= N_EDG) return;
  int col = ei[N_EDG + e];
  if ((unsigned)col < (unsigned)M_NODES) atomicAdd(&deg[col], 1);
}

__global__ void k_dis(const int* __restrict__ deg, float* __restrict__ dis) {
  int i = blockIdx.x * blockDim.x + threadIdx.x;
  if (i >= M_NODES) return;
  int d = deg[i];
  dis[i] = (d > 0) ? rsqrtf((float)d) : 0.0f;
}

__global__ void k_norm(const int* __restrict__ ei,
                       const float* __restrict__ dis,
                       float* __restrict__ norm) {
  int e = blockIdx.x * blockDim.x + threadIdx.x;
  if (e >= N_EDG) return;
  int row = ei[e];
  int col = ei[N_EDG + e];
  float v = 0.0f;
  if ((unsigned)row < (unsigned)M_NODES && (unsigned)col < (unsigned)M_NODES)
    v = dis[row] * dis[col];
  norm[e] = v;
}

// ---------------- SpMM hop: out[col] += norm_e * h[row] (out pre-seeded) --------
template <int D>
__global__ void k_spmm(float* __restrict__ out, const float* __restrict__ h,
                       const int* __restrict__ ei,
                       const float* __restrict__ norm) {
  constexpr int CH = D / 4;
  long long tid = (long long)blockIdx.x * blockDim.x + threadIdx.x;
  if (tid >= (long long)N_EDG * CH) return;
  int c = (int)(tid % CH);
  int e = (int)(tid / CH);
  int row = __ldg(&ei[e]);
  int col = __ldg(&ei[N_EDG + e]);
  if ((unsigned)row >= (unsigned)M_NODES || (unsigned)col >= (unsigned)M_NODES) return;
  float nm = __ldg(&norm[e]);
  const float4 v = *(const float4*)(h + (size_t)row * D + c * 4);
  float4 r;
  r.x = v.x * nm; r.y = v.y * nm; r.z = v.z * nm; r.w = v.w * nm;
  float* dst = out + (size_t)col * D + c * 4;
  asm volatile("red.global.add.v4.f32 [%0], {%1, %2, %3, %4};"
               :: "l"(dst), "f"(r.x), "f"(r.y), "f"(r.z), "f"(r.w)
               : "memory");
}

// ---------------- fused 4-plane GEMM ----------------
// Computes out_cat[M, 4*NOUT] = in[M,KTOT] @ W[4*NOUT,KTOT]^T, routing column
// block n to plane n/NOUT (p0..p3); bias added to plane 0 only.
// Register tiled: 8x8 per thread, packed f32x2 accumulation.
template <int BM, int BN, int BK, int NOUT, int KTOT>
__global__ void __launch_bounds__((BM / 8) * (BN / 8))
k_gemm4(float* __restrict__ p0, float* __restrict__ p1,
        float* __restrict__ p2, float* __restrict__ p3,
        const float* __restrict__ in, const float* __restrict__ W,
        const float* __restrict__ bias) {
  constexpr int NT = (BM / 8) * (BN / 8);
  __shared__ float sA[BK][BM];   // transposed in-tile
  __shared__ float sB[BK][BN];   // transposed W-tile
  const int tid = threadIdx.x;
  const int m0 = blockIdx.x * BM;
  const int n0 = blockIdx.y * BN;
  const int tn = (tid % (BN / 8)) * 8;
  const int tm = (tid / (BN / 8)) * 8;

  unsigned long long acc[8][4];
#pragma unroll
  for (int i = 0; i < 8; i++)
#pragma unroll
    for (int j = 0; j < 4; j++) acc[i][j] = 0ull;

  for (int kt = 0; kt < KTOT; kt += BK) {
#pragma unroll
    for (int idx = tid; idx < BM * BK / 4; idx += NT) {
      int row = idx / (BK / 4);
      int kq  = idx % (BK / 4);
      float4 v = make_float4(0.f, 0.f, 0.f, 0.f);
      int m = m0 + row;
      if (m < M_NODES)
        v = *(const float4*)(in + (size_t)m * KTOT + kt + kq * 4);
      sA[kq * 4 + 0][row] = v.x; sA[kq * 4 + 1][row] = v.y;
      sA[kq * 4 + 2][row] = v.z; sA[kq * 4 + 3][row] = v.w;
    }
#pragma unroll
    for (int idx = tid; idx < BN * BK / 4; idx += NT) {
      int row = idx / (BK / 4);
      int kq  = idx % (BK / 4);
      float4 v = *(const float4*)(W + (size_t)(n0 + row) * KTOT + kt + kq * 4);
      sB[kq * 4 + 0][row] = v.x; sB[kq * 4 + 1][row] = v.y;
      sB[kq * 4 + 2][row] = v.z; sB[kq * 4 + 3][row] = v.w;
    }
    __syncthreads();
#pragma unroll
    for (int k = 0; k < BK; k++) {
      float4 a0 = *(const float4*)&sA[k][tm];
      float4 a1 = *(const float4*)&sA[k][tm + 4];
      ulonglong2 bl0 = *(const ulonglong2*)&sB[k][tn];
      ulonglong2 bl1 = *(const ulonglong2*)&sB[k][tn + 4];
      unsigned long long bp[4] = {bl0.x, bl0.y, bl1.x, bl1.y};
      float av[8] = {a0.x, a0.y, a0.z, a0.w, a1.x, a1.y, a1.z, a1.w};
#pragma unroll
      for (int i = 0; i < 8; i++) {
        unsigned long long ap = pack2(av[i]);
#pragma unroll
        for (int j = 0; j < 4; j++) acc[i][j] = ffma2(ap, bp[j], acc[i][j]);
      }
    }
    __syncthreads();
  }

  // epilogue: thread's 8-wide n-slab lies in exactly one plane (8 | NOUT)
  const int plane = (n0 + tn) / NOUT;
  const int col   = (n0 + tn) % NOUT;
  float* outp = (plane == 0) ? p0 : (plane == 1) ? p1 : (plane == 2) ? p2 : p3;
  float bv[8];
#pragma unroll
  for (int j = 0; j < 8; j++) bv[j] = (plane == 0) ? bias[col + j] : 0.0f;
#pragma unroll
  for (int i = 0; i < 8; i++) {
    int m = m0 + tm + i;
    if (m >= M_NODES) break;
    float2 r[4];
#pragma unroll
    for (int j = 0; j < 4; j++) {
      r[j] = *reinterpret_cast<float2*>(&acc[i][j]);
      r[j].x += bv[2 * j]; r[j].y += bv[2 * j + 1];
    }
    float4 w0 = make_float4(r[0].x, r[0].y, r[1].x, r[1].y);
    float4 w1 = make_float4(r[2].x, r[2].y, r[3].x, r[3].y);
    *(float4*)(outp + (size_t)m * NOUT + col)     = w0;
    *(float4*)(outp + (size_t)m * NOUT + col + 4) = w1;
  }
}

// ---------------- dropout (+ optional ELU first) ----------------
#if JAX_PARTITIONABLE
template <bool ELU>
__global__ void k_dropout(float* p, int n, unsigned k0, unsigned k1) {
  int i = blockIdx.x * blockDim.x + threadIdx.x;
  if (i >= n) return;
  unsigned o0, o1;
  threefry2x32(k0, k1, 0u, (unsigned)i, o0, o1);
  unsigned bits = o0 ^ o1;
  float u = __uint_as_float((bits >> 9) | 0x3F800000u) - 1.0f;
  float v = p[i];
  if (ELU) v = (v > 0.0f) ? v : expm1f(v);
  p[i] = (u < 0.5f) ? v * 2.0f : 0.0f;
}
#else
template <bool ELU>
__global__ void k_dropout(float* p, int n, unsigned k0, unsigned k1) {
  int j = blockIdx.x * blockDim.x + threadIdx.x;
  int half = n / 2;
  if (j >= half) return;
  unsigned o0, o1;
  threefry2x32(k0, k1, (unsigned)j, (unsigned)(j + half), o0, o1);
  float u0 = __uint_as_float((o0 >> 9) | 0x3F800000u) - 1.0f;
  float u1 = __uint_as_float((o1 >> 9) | 0x3F800000u) - 1.0f;
  float v0 = p[j], v1 = p[j + half];
  if (ELU) {
    v0 = (v0 > 0.0f) ? v0 : expm1f(v0);
    v1 = (v1 > 0.0f) ? v1 : expm1f(v1);
  }
  p[j]        = (u0 < 0.5f) ? v0 * 2.0f : 0.0f;
  p[j + half] = (u1 < 0.5f) ? v1 * 2.0f : 0.0f;
}
#endif

// ---------------- host orchestration ----------------
static inline int cdiv(long long a, int b) { return (int)((a + b - 1) / b); }

extern "C" void kernel_launch(void* const* d_in, const int* in_sizes, int n_in,
                              void* d_out, int out_size) {
  const float* x  = (const float*)d_in[0];
  const int*   ei = (const int*)d_in[1];   // int32 (JAX x64 disabled)
  const float* W1 = (const float*)d_in[2];
  const float* b1 = (const float*)d_in[3];
  const float* W2 = (const float*)d_in[4];
  const float* b2 = (const float*)d_in[5];
  const float* W3 = (const float*)d_in[6];
  const float* b3 = (const float*)d_in[7];
  float* out = (float*)d_out;

  int* deg; float *dis, *norm, *bA, *bB, *bC, *bD, *bE;
  cudaGetSymbolAddress((void**)&deg,  g_deg);
  cudaGetSymbolAddress((void**)&dis,  g_dis);
  cudaGetSymbolAddress((void**)&norm, g_norm);
  cudaGetSymbolAddress((void**)&bA,   g_bufA);
  cudaGetSymbolAddress((void**)&bB,   g_bufB);
  cudaGetSymbolAddress((void**)&bC,   g_bufC);
  cudaGetSymbolAddress((void**)&bD,   g_bufD);
  cudaGetSymbolAddress((void**)&bE,   g_bufE);

  unsigned dk1a, dk1b, dk2a, dk2b;
#if JAX_PARTITIONABLE
  threefry2x32(0u, 42u, 0u, 0u, dk1a, dk1b);
  threefry2x32(0u, 42u, 0u, 1u, dk2a, dk2b);
#else
  unsigned a0, a1, c0, c1;
  threefry2x32(0u, 42u, 0u, 2u, a0, c0);
  threefry2x32(0u, 42u, 1u, 3u, a1, c1);
  dk1a = a0; dk1b = a1; dk2a = c0; dk2b = c1;
#endif

  const int T = 256;
  const int GM = cdiv(M_NODES, 128);   // 782 row-blocks

  // ---- degree / norm ----
  k_zero_i<<<cdiv(M_NODES, T), T>>>(deg, M_NODES);
  k_deg  <<<cdiv(N_EDG,   T), T>>>(ei, deg);
  k_dis  <<<cdiv(M_NODES, T), T>>>(deg, dis);
  k_norm <<<cdiv(N_EDG,   T), T>>>(ei, dis, norm);

  // Horner per layer: P_k = h @ W_k^T; P2 += A P3; P1 += A P2; P0 += A P1.

  // ---- layer 1: 128 -> 128.  planes A(P0+b1), B, C, D.  h = x ----
  {
    const int N = 128;
    k_gemm4<128, 128, 16, 128, 128><<<dim3(GM, 4), 256>>>(bA, bB, bC, bD, x, W1, b1);
    k_spmm<N><<<cdiv((long long)N_EDG * (N / 4), T), T>>>(bC, bD, ei, norm);
    k_spmm<N><<<cdiv((long long)N_EDG * (N / 4), T), T>>>(bB, bC, ei, norm);
    k_spmm<N><<<cdiv((long long)N_EDG * (N / 4), T), T>>>(bA, bB, ei, norm);
    k_dropout<false><<<cdiv((long long)M_NODES * N, T), T>>>(bA, M_NODES * N, dk1a, dk1b);
  }

  // ---- layer 2: 128 -> 64.  planes B(P0+b2), C, D, E.  h = bA ----
  {
    const int N = 64;
    k_gemm4<128, 128, 16, 64, 128><<<dim3(GM, 2), 256>>>(bB, bC, bD, bE, bA, W2, b2);
    k_spmm<N><<<cdiv((long long)N_EDG * (N / 4), T), T>>>(bD, bE, ei, norm);
    k_spmm<N><<<cdiv((long long)N_EDG * (N / 4), T), T>>>(bC, bD, ei, norm);
    k_spmm<N><<<cdiv((long long)N_EDG * (N / 4), T), T>>>(bB, bC, ei, norm);
    k_dropout<true><<<cdiv((long long)M_NODES * N, T), T>>>(bB, M_NODES * N, dk2a, dk2b);
  }

  // ---- layer 3: 64 -> 16.  planes out(P0+b3), C, D, E.  h = bB ----
  {
    const int N = 16;
    k_gemm4<128, 64, 16, 16, 64><<<dim3(GM, 1), 128>>>(out, bC, bD, bE, bB, W3, b3);
    k_spmm<N><<<cdiv((long long)N_EDG * (N / 4), T), T>>>(bD,  bE, ei, norm);
    k_spmm<N><<<cdiv((long long)N_EDG * (N / 4), T), T>>>(bC,  bD, ei, norm);
    k_spmm<N><<<cdiv((long long)N_EDG * (N / 4), T), T>>>(out, bC, ei, norm);
  }
}

// round 6
// speedup vs baseline: 3.0947x; 1.6137x over previous
#include <cuda_runtime.h>
#include <cstdint>
#include <cstddef>

#define M_NODES 100000
#define N_EDG   1600000
#define JAX_PARTITIONABLE 1

// ---------------- scratch (static device globals; no allocation) ----------------
__device__ int   g_deg[M_NODES];
__device__ int   g_fill[M_NODES];
__device__ int   g_rptr[M_NODES + 1];
__device__ int   g_src[N_EDG];
__device__ float g_w[N_EDG];
__device__ float g_dis[M_NODES];
__device__ __align__(16) float g_bufA[(size_t)M_NODES * 128];
__device__ __align__(16) float g_bufB[(size_t)M_NODES * 128];
__device__ __align__(16) float g_bufC[(size_t)M_NODES * 128];
__device__ __align__(16) float g_bufD[(size_t)M_NODES * 128];
__device__ __align__(16) float g_bufE[(size_t)M_NODES * 128];

// ---------------- threefry2x32 ----------------
__host__ __device__ __forceinline__ unsigned tf_rotl(unsigned x, int r) {
  return (x << r) | (x >> (32 - r));
}

__host__ __device__ __forceinline__ void threefry2x32(
    unsigned k0, unsigned k1, unsigned x0, unsigned x1,
    unsigned& o0, unsigned& o1) {
  unsigned ks2 = k0 ^ k1 ^ 0x1BD11BDAu;
  x0 += k0; x1 += k1;
#define TF_R(r) { x0 += x1; x1 = tf_rotl(x1, (r)); x1 ^= x0; }
  TF_R(13) TF_R(15) TF_R(26) TF_R(6)
  x0 += k1;  x1 += ks2 + 1u;
  TF_R(17) TF_R(29) TF_R(16) TF_R(24)
  x0 += ks2; x1 += k0 + 2u;
  TF_R(13) TF_R(15) TF_R(26) TF_R(6)
  x0 += k0;  x1 += k1 + 3u;
  TF_R(17) TF_R(29) TF_R(16) TF_R(24)
  x0 += k1;  x1 += ks2 + 4u;
  TF_R(13) TF_R(15) TF_R(26) TF_R(6)
  x0 += ks2; x1 += k0 + 5u;
#undef TF_R
  o0 = x0; o1 = x1;
}

// ---------------- f32x2 packed helpers ----------------
__device__ __forceinline__ unsigned long long pack2(float a) {
  unsigned long long r;
  asm("mov.b64 %0, {%1, %1};" : "=l"(r) : "r"(__float_as_uint(a)));
  return r;
}
__device__ __forceinline__ unsigned long long ffma2(
    unsigned long long a, unsigned long long b, unsigned long long c) {
  unsigned long long d;
  asm("fma.rn.f32x2 %0, %1, %2, %3;" : "=l"(d) : "l"(a), "l"(b), "l"(c));
  return d;
}

// ---------------- CSR build pipeline ----------------
__global__ void k_zero_i2(int* p, int* q, int n) {
  int i = blockIdx.x * blockDim.x + threadIdx.x;
  if (i < n) { p[i] = 0; q[i] = 0; }
}

__global__ void k_deg(const int* __restrict__ ei, int* __restrict__ deg) {
  int e = blockIdx.x * blockDim.x + threadIdx.x;
  if (e >= N_EDG) return;
  int col = ei[N_EDG + e];
  if ((unsigned)col < (unsigned)M_NODES) atomicAdd(&deg[col], 1);
}

__global__ void k_dis(const int* __restrict__ deg, float* __restrict__ dis) {
  int i = blockIdx.x * blockDim.x + threadIdx.x;
  if (i >= M_NODES) return;
  int d = deg[i];
  dis[i] = (d > 0) ? rsqrtf((float)d) : 0.0f;
}

// single-block exclusive scan: 1024 threads x 98 elements
__global__ void __launch_bounds__(1024, 1)
k_scan(const int* __restrict__ deg, int* __restrict__ rptr) {
  __shared__ int sh[1024];
  const int t = threadIdx.x;
  const int CH = (M_NODES + 1023) / 1024;  // 98
  const int base = t * CH;
  int s = 0;
#pragma unroll 1
  for (int i = 0; i < CH; i++) {
    int idx = base + i;
    if (idx < M_NODES) s += deg[idx];
  }
  sh[t] = s;
  __syncthreads();
#pragma unroll 1
  for (int off = 1; off < 1024; off <<= 1) {
    int v = (t >= off) ? sh[t - off] : 0;
    __syncthreads();
    sh[t] += v;
    __syncthreads();
  }
  int run = (t == 0) ? 0 : sh[t - 1];
#pragma unroll 1
  for (int i = 0; i < CH; i++) {
    int idx = base + i;
    if (idx < M_NODES) { rptr[idx] = run; run += deg[idx]; }
  }
  if (t == 1023) rptr[M_NODES] = run;
}

__global__ void k_scatter(const int* __restrict__ ei, const float* __restrict__ dis,
                          const int* __restrict__ rptr, int* __restrict__ fill,
                          int* __restrict__ src, float* __restrict__ w) {
  int e = blockIdx.x * blockDim.x + threadIdx.x;
  if (e >= N_EDG) return;
  int row = ei[e];
  int col = ei[N_EDG + e];
  if ((unsigned)row >= (unsigned)M_NODES || (unsigned)col >= (unsigned)M_NODES) return;
  int pos = rptr[col] + atomicAdd(&fill[col], 1);
  src[pos] = row;
  w[pos] = dis[row] * dis[col];
}

// ---------------- CSR gather SpMM: out[n] += sum_e w[e] * h[src[e]] ----------------
// D/4 threads per node (float4 lanes); out pre-seeded with the Horner plane.
template <int D>
__global__ void __launch_bounds__(128)
k_spmm_csr(float* __restrict__ out, const float* __restrict__ h,
           const int* __restrict__ rptr,
           const int* __restrict__ src,
           const float* __restrict__ w) {
  constexpr int TPN = D / 4;
  constexpr int NPB = 128 / TPN;
  int tid = threadIdx.x;
  int node = blockIdx.x * NPB + tid / TPN;
  if (node >= M_NODES) return;
  int c = (tid % TPN) * 4;
  int e0 = __ldg(&rptr[node]);
  int e1 = __ldg(&rptr[node + 1]);
  float4 acc = *(float4*)(out + (size_t)node * D + c);
  for (int e = e0; e < e1; e++) {
    int s = __ldg(&src[e]);
    float nm = __ldg(&w[e]);
    const float4 v = *(const float4*)(h + (size_t)s * D + c);
    acc.x = fmaf(nm, v.x, acc.x);
    acc.y = fmaf(nm, v.y, acc.y);
    acc.z = fmaf(nm, v.z, acc.z);
    acc.w = fmaf(nm, v.w, acc.w);
  }
  *(float4*)(out + (size_t)node * D + c) = acc;
}

// ---------------- fused 4-plane GEMM ----------------
template <int BM, int BN, int BK, int NOUT, int KTOT>
__global__ void __launch_bounds__((BM / 8) * (BN / 8))
k_gemm4(float* __restrict__ p0, float* __restrict__ p1,
        float* __restrict__ p2, float* __restrict__ p3,
        const float* __restrict__ in, const float* __restrict__ W,
        const float* __restrict__ bias) {
  constexpr int NT = (BM / 8) * (BN / 8);
  __shared__ float sA[BK][BM];
  __shared__ float sB[BK][BN];
  const int tid = threadIdx.x;
  const int m0 = blockIdx.x * BM;
  const int n0 = blockIdx.y * BN;
  const int tn = (tid % (BN / 8)) * 8;
  const int tm = (tid / (BN / 8)) * 8;

  unsigned long long acc[8][4];
#pragma unroll
  for (int i = 0; i < 8; i++)
#pragma unroll
    for (int j = 0; j < 4; j++) acc[i][j] = 0ull;

  for (int kt = 0; kt < KTOT; kt += BK) {
#pragma unroll
    for (int idx = tid; idx < BM * BK / 4; idx += NT) {
      int row = idx / (BK / 4);
      int kq  = idx % (BK / 4);
      float4 v = make_float4(0.f, 0.f, 0.f, 0.f);
      int m = m0 + row;
      if (m < M_NODES)
        v = *(const float4*)(in + (size_t)m * KTOT + kt + kq * 4);
      sA[kq * 4 + 0][row] = v.x; sA[kq * 4 + 1][row] = v.y;
      sA[kq * 4 + 2][row] = v.z; sA[kq * 4 + 3][row] = v.w;
    }
#pragma unroll
    for (int idx = tid; idx < BN * BK / 4; idx += NT) {
      int row = idx / (BK / 4);
      int kq  = idx % (BK / 4);
      float4 v = *(const float4*)(W + (size_t)(n0 + row) * KTOT + kt + kq * 4);
      sB[kq * 4 + 0][row] = v.x; sB[kq * 4 + 1][row] = v.y;
      sB[kq * 4 + 2][row] = v.z; sB[kq * 4 + 3][row] = v.w;
    }
    __syncthreads();
#pragma unroll
    for (int k = 0; k < BK; k++) {
      float4 a0 = *(const float4*)&sA[k][tm];
      float4 a1 = *(const float4*)&sA[k][tm + 4];
      ulonglong2 bl0 = *(const ulonglong2*)&sB[k][tn];
      ulonglong2 bl1 = *(const ulonglong2*)&sB[k][tn + 4];
      unsigned long long bp[4] = {bl0.x, bl0.y, bl1.x, bl1.y};
      float av[8] = {a0.x, a0.y, a0.z, a0.w, a1.x, a1.y, a1.z, a1.w};
#pragma unroll
      for (int i = 0; i < 8; i++) {
        unsigned long long ap = pack2(av[i]);
#pragma unroll
        for (int j = 0; j < 4; j++) acc[i][j] = ffma2(ap, bp[j], acc[i][j]);
      }
    }
    __syncthreads();
  }

  const int plane = (n0 + tn) / NOUT;
  const int col   = (n0 + tn) % NOUT;
  float* outp = (plane == 0) ? p0 : (plane == 1) ? p1 : (plane == 2) ? p2 : p3;
  float bv[8];
#pragma unroll
  for (int j = 0; j < 8; j++) bv[j] = (plane == 0) ? bias[col + j] : 0.0f;
#pragma unroll
  for (int i = 0; i < 8; i++) {
    int m = m0 + tm + i;
    if (m >= M_NODES) break;
    float2 r[4];
#pragma unroll
    for (int j = 0; j < 4; j++) {
      r[j] = *reinterpret_cast<float2*>(&acc[i][j]);
      r[j].x += bv[2 * j]; r[j].y += bv[2 * j + 1];
    }
    float4 w0 = make_float4(r[0].x, r[0].y, r[1].x, r[1].y);
    float4 w1 = make_float4(r[2].x, r[2].y, r[3].x, r[3].y);
    *(float4*)(outp + (size_t)m * NOUT + col)     = w0;
    *(float4*)(outp + (size_t)m * NOUT + col + 4) = w1;
  }
}

// ---------------- dropout (+ optional ELU first) ----------------
#if JAX_PARTITIONABLE
template <bool ELU>
__global__ void k_dropout(float* p, int n, unsigned k0, unsigned k1) {
  int i = blockIdx.x * blockDim.x + threadIdx.x;
  if (i >= n) return;
  unsigned o0, o1;
  threefry2x32(k0, k1, 0u, (unsigned)i, o0, o1);
  unsigned bits = o0 ^ o1;
  float u = __uint_as_float((bits >> 9) | 0x3F800000u) - 1.0f;
  float v = p[i];
  if (ELU) v = (v > 0.0f) ? v : expm1f(v);
  p[i] = (u < 0.5f) ? v * 2.0f : 0.0f;
}
#else
template <bool ELU>
__global__ void k_dropout(float* p, int n, unsigned k0, unsigned k1) {
  int j = blockIdx.x * blockDim.x + threadIdx.x;
  int half = n / 2;
  if (j >= half) return;
  unsigned o0, o1;
  threefry2x32(k0, k1, (unsigned)j, (unsigned)(j + half), o0, o1);
  float u0 = __uint_as_float((o0 >> 9) | 0x3F800000u) - 1.0f;
  float u1 = __uint_as_float((o1 >> 9) | 0x3F800000u) - 1.0f;
  float v0 = p[j], v1 = p[j + half];
  if (ELU) {
    v0 = (v0 > 0.0f) ? v0 : expm1f(v0);
    v1 = (v1 > 0.0f) ? v1 : expm1f(v1);
  }
  p[j]        = (u0 < 0.5f) ? v0 * 2.0f : 0.0f;
  p[j + half] = (u1 < 0.5f) ? v1 * 2.0f : 0.0f;
}
#endif

// ---------------- host orchestration ----------------
static inline int cdiv(long long a, int b) { return (int)((a + b - 1) / b); }

extern "C" void kernel_launch(void* const* d_in, const int* in_sizes, int n_in,
                              void* d_out, int out_size) {
  const float* x  = (const float*)d_in[0];
  const int*   ei = (const int*)d_in[1];   // int32 (JAX x64 disabled)
  const float* W1 = (const float*)d_in[2];
  const float* b1 = (const float*)d_in[3];
  const float* W2 = (const float*)d_in[4];
  const float* b2 = (const float*)d_in[5];
  const float* W3 = (const float*)d_in[6];
  const float* b3 = (const float*)d_in[7];
  float* out = (float*)d_out;

  int *deg, *fill, *rptr, *srcv;
  float *dis, *wv, *bA, *bB, *bC, *bD, *bE;
  cudaGetSymbolAddress((void**)&deg,  g_deg);
  cudaGetSymbolAddress((void**)&fill, g_fill);
  cudaGetSymbolAddress((void**)&rptr, g_rptr);
  cudaGetSymbolAddress((void**)&srcv, g_src);
  cudaGetSymbolAddress((void**)&wv,   g_w);
  cudaGetSymbolAddress((void**)&dis,  g_dis);
  cudaGetSymbolAddress((void**)&bA,   g_bufA);
  cudaGetSymbolAddress((void**)&bB,   g_bufB);
  cudaGetSymbolAddress((void**)&bC,   g_bufC);
  cudaGetSymbolAddress((void**)&bD,   g_bufD);
  cudaGetSymbolAddress((void**)&bE,   g_bufE);

  unsigned dk1a, dk1b, dk2a, dk2b;
#if JAX_PARTITIONABLE
  threefry2x32(0u, 42u, 0u, 0u, dk1a, dk1b);
  threefry2x32(0u, 42u, 0u, 1u, dk2a, dk2b);
#else
  unsigned a0, a1, c0, c1;
  threefry2x32(0u, 42u, 0u, 2u, a0, c0);
  threefry2x32(0u, 42u, 1u, 3u, a1, c1);
  dk1a = a0; dk1b = a1; dk2a = c0; dk2b = c1;
#endif

  const int T = 256;
  const int GM = cdiv(M_NODES, 128);

  // ---- CSR build: deg -> dis -> rptr -> scatter(src, w) ----
  k_zero_i2<<<cdiv(M_NODES, T), T>>>(deg, fill, M_NODES);
  k_deg    <<<cdiv(N_EDG,   T), T>>>(ei, deg);
  k_dis    <<<cdiv(M_NODES, T), T>>>(deg, dis);
  k_scan   <<<1, 1024>>>(deg, rptr);
  k_scatter<<<cdiv(N_EDG,   T), T>>>(ei, dis, rptr, fill, srcv, wv);

  // Horner per layer: P_k = h @ W_k^T; P2 += A P3; P1 += A P2; P0 += A P1.

  // ---- layer 1: 128 -> 128.  planes A(P0+b1), B, C, D.  h = x ----
  {
    const int N = 128;
    k_gemm4<128, 128, 16, 128, 128><<<dim3(GM, 4), 256>>>(bA, bB, bC, bD, x, W1, b1);
    const int NPB = 128 / (N / 4);
    k_spmm_csr<N><<<cdiv(M_NODES, NPB), 128>>>(bC, bD, rptr, srcv, wv);
    k_spmm_csr<N><<<cdiv(M_NODES, NPB), 128>>>(bB, bC, rptr, srcv, wv);
    k_spmm_csr<N><<<cdiv(M_NODES, NPB), 128>>>(bA, bB, rptr, srcv, wv);
    k_dropout<false><<<cdiv((long long)M_NODES * N, T), T>>>(bA, M_NODES * N, dk1a, dk1b);
  }

  // ---- layer 2: 128 -> 64.  planes B(P0+b2), C, D, E.  h = bA ----
  {
    const int N = 64;
    k_gemm4<128, 128, 16, 64, 128><<<dim3(GM, 2), 256>>>(bB, bC, bD, bE, bA, W2, b2);
    const int NPB = 128 / (N / 4);
    k_spmm_csr<N><<<cdiv(M_NODES, NPB), 128>>>(bD, bE, rptr, srcv, wv);
    k_spmm_csr<N><<<cdiv(M_NODES, NPB), 128>>>(bC, bD, rptr, srcv, wv);
    k_spmm_csr<N><<<cdiv(M_NODES, NPB), 128>>>(bB, bC, rptr, srcv, wv);
    k_dropout<true><<<cdiv((long long)M_NODES * N, T), T>>>(bB, M_NODES * N, dk2a, dk2b);
  }

  // ---- layer 3: 64 -> 16.  planes out(P0+b3), C, D, E.  h = bB ----
  {
    const int N = 16;
    k_gemm4<128, 64, 16, 16, 64><<<dim3(GM, 1), 128>>>(out, bC, bD, bE, bB, W3, b3);
    const int NPB = 128 / (N / 4);
    k_spmm_csr<N><<<cdiv(M_NODES, NPB), 128>>>(bD,  bE, rptr, srcv, wv);
    k_spmm_csr<N><<<cdiv(M_NODES, NPB), 128>>>(bC,  bD, rptr, srcv, wv);
    k_spmm_csr<N><<<cdiv(M_NODES, NPB), 128>>>(out, bC, rptr, srcv, wv);
  }
}

// round 11
// speedup vs baseline: 3.4104x; 1.1020x over previous
#include <cuda_runtime.h>
#include <cstdint>
#include <cstddef>

#define M_NODES 100000
#define N_EDG   1600000
#define JAX_PARTITIONABLE 1
#define SCAN_B 98   // ceil(M_NODES / 1024)

// ---------------- scratch (static device globals; no allocation) ----------------
__device__ int   g_deg[M_NODES];
__device__ int   g_fill[M_NODES];
__device__ int   g_rptr[M_NODES + 1];
__device__ int   g_bsum[SCAN_B];
__device__ int   g_boff[SCAN_B + 1];
__device__ int   g_src[N_EDG];
__device__ float g_w[N_EDG];
__device__ float g_dis[M_NODES];
__device__ __align__(16) float g_bufA[(size_t)M_NODES * 128];
__device__ __align__(16) float g_bufB[(size_t)M_NODES * 128];
__device__ __align__(16) float g_bufC[(size_t)M_NODES * 128];
__device__ __align__(16) float g_bufD[(size_t)M_NODES * 128];
__device__ __align__(16) float g_bufE[(size_t)M_NODES * 128];

// ---------------- threefry2x32 ----------------
__host__ __device__ __forceinline__ unsigned tf_rotl(unsigned x, int r) {
  return (x << r) | (x >> (32 - r));
}

__host__ __device__ __forceinline__ void threefry2x32(
    unsigned k0, unsigned k1, unsigned x0, unsigned x1,
    unsigned& o0, unsigned& o1) {
  unsigned ks2 = k0 ^ k1 ^ 0x1BD11BDAu;
  x0 += k0; x1 += k1;
#define TF_R(r) { x0 += x1; x1 = tf_rotl(x1, (r)); x1 ^= x0; }
  TF_R(13) TF_R(15) TF_R(26) TF_R(6)
  x0 += k1;  x1 += ks2 + 1u;
  TF_R(17) TF_R(29) TF_R(16) TF_R(24)
  x0 += ks2; x1 += k0 + 2u;
  TF_R(13) TF_R(15) TF_R(26) TF_R(6)
  x0 += k0;  x1 += k1 + 3u;
  TF_R(17) TF_R(29) TF_R(16) TF_R(24)
  x0 += k1;  x1 += ks2 + 4u;
  TF_R(13) TF_R(15) TF_R(26) TF_R(6)
  x0 += ks2; x1 += k0 + 5u;
#undef TF_R
  o0 = x0; o1 = x1;
}

// ---------------- f32x2 packed helpers ----------------
__device__ __forceinline__ unsigned long long pack2(float a) {
  unsigned long long r;
  asm("mov.b64 %0, {%1, %1};" : "=l"(r) : "r"(__float_as_uint(a)));
  return r;
}
__device__ __forceinline__ unsigned long long ffma2(
    unsigned long long a, unsigned long long b, unsigned long long c) {
  unsigned long long d;
  asm("fma.rn.f32x2 %0, %1, %2, %3;" : "=l"(d) : "l"(a), "l"(b), "l"(c));
  return d;
}

// ---------------- CSR build pipeline ----------------
__global__ void k_zero_i2(int* p, int* q, int n) {
  int i = blockIdx.x * blockDim.x + threadIdx.x;
  if (i < n) { p[i] = 0; q[i] = 0; }
}

__global__ void k_deg(const int* __restrict__ ei, int* __restrict__ deg) {
  int e = blockIdx.x * blockDim.x + threadIdx.x;
  if (e >= N_EDG) return;
  int col = ei[N_EDG + e];
  if ((unsigned)col < (unsigned)M_NODES) atomicAdd(&deg[col], 1);
}

// phase 1: per-block exclusive prefix into rptr, block totals into bsum; also dis.
__global__ void __launch_bounds__(1024)
k_scan1(const int* __restrict__ deg, int* __restrict__ rptr,
        int* __restrict__ bsum, float* __restrict__ dis) {
  __shared__ int sh[1024];
  int t = threadIdx.x;
  int idx = blockIdx.x * 1024 + t;
  int v = (idx < M_NODES) ? deg[idx] : 0;
  if (idx < M_NODES) dis[idx] = (v > 0) ? rsqrtf((float)v) : 0.0f;
  sh[t] = v;
  __syncthreads();
  int run = v;
  for (int off = 1; off < 1024; off <<= 1) {
    int u = (t >= off) ? sh[t - off] : 0;
    __syncthreads();
    run += u;
    sh[t] = run;
    __syncthreads();
  }
  if (idx < M_NODES) rptr[idx] = run - v;   // exclusive within block
  if (t == 1023) bsum[blockIdx.x] = run;
}

// phase 2: scan SCAN_B block sums -> boff[0..SCAN_B] (exclusive, last = total).
__global__ void __launch_bounds__(128)
k_scan2(const int* __restrict__ bsum, int* __restrict__ boff) {
  __shared__ int sh[SCAN_B];
  int t = threadIdx.x;
  if (t < SCAN_B) sh[t] = bsum[t];
  __syncthreads();
  if (t == 0) {
    int run = 0;
    for (int i = 0; i < SCAN_B; i++) {
      int v = sh[i];
      boff[i] = run;
      run += v;
    }
    boff[SCAN_B] = run;
  }
}

// phase 3: add block offsets; write rptr[M].
__global__ void __launch_bounds__(1024)
k_scan3(int* __restrict__ rptr, const int* __restrict__ boff) {
  int t = threadIdx.x;
  int idx = blockIdx.x * 1024 + t;
  if (idx < M_NODES) rptr[idx] += boff[blockIdx.x];
  if (idx == 0) rptr[M_NODES] = boff[SCAN_B];
}

__global__ void k_scatter(const int* __restrict__ ei, const float* __restrict__ dis,
                          const int* __restrict__ rptr, int* __restrict__ fill,
                          int* __restrict__ src, float* __restrict__ w) {
  int e = blockIdx.x * blockDim.x + threadIdx.x;
  if (e >= N_EDG) return;
  int row = ei[e];
  int col = ei[N_EDG + e];
  if ((unsigned)row >= (unsigned)M_NODES || (unsigned)col >= (unsigned)M_NODES) return;
  int pos = rptr[col] + atomicAdd(&fill[col], 1);
  src[pos] = row;
  w[pos] = dis[row] * dis[col];
}

// ---------------- CSR gather SpMM: out[n] += sum_e w[e] * h[src[e]] ----------------
template <int D>
__global__ void __launch_bounds__(128)
k_spmm_csr(float* __restrict__ out, const float* __restrict__ h,
           const int* __restrict__ rptr,
           const int* __restrict__ src,
           const float* __restrict__ w) {
  constexpr int TPN = D / 4;
  constexpr int NPB = 128 / TPN;
  int tid = threadIdx.x;
  int node = blockIdx.x * NPB + tid / TPN;
  if (node >= M_NODES) return;
  int c = (tid % TPN) * 4;
  int e0 = __ldg(&rptr[node]);
  int e1 = __ldg(&rptr[node + 1]);
  float4 acc = *(float4*)(out + (size_t)node * D + c);
  for (int e = e0; e < e1; e++) {
    int s = __ldg(&src[e]);
    float nm = __ldg(&w[e]);
    const float4 v = *(const float4*)(h + (size_t)s * D + c);
    acc.x = fmaf(nm, v.x, acc.x);
    acc.y = fmaf(nm, v.y, acc.y);
    acc.z = fmaf(nm, v.z, acc.z);
    acc.w = fmaf(nm, v.w, acc.w);
  }
  *(float4*)(out + (size_t)node * D + c) = acc;
}

// ---------------- fused 4-plane GEMM ----------------
template <int BM, int BN, int BK, int NOUT, int KTOT>
__global__ void __launch_bounds__((BM / 8) * (BN / 8))
k_gemm4(float* __restrict__ p0, float* __restrict__ p1,
        float* __restrict__ p2, float* __restrict__ p3,
        const float* __restrict__ in, const float* __restrict__ W,
        const float* __restrict__ bias) {
  constexpr int NT = (BM / 8) * (BN / 8);
  __shared__ float sA[BK][BM];
  __shared__ float sB[BK][BN];
  const int tid = threadIdx.x;
  const int m0 = blockIdx.x * BM;
  const int n0 = blockIdx.y * BN;
  const int tn = (tid % (BN / 8)) * 8;
  const int tm = (tid / (BN / 8)) * 8;

  unsigned long long acc[8][4];
#pragma unroll
  for (int i = 0; i < 8; i++)
#pragma unroll
    for (int j = 0; j < 4; j++) acc[i][j] = 0ull;

  for (int kt = 0; kt < KTOT; kt += BK) {
#pragma unroll
    for (int idx = tid; idx < BM * BK / 4; idx += NT) {
      int row = idx / (BK / 4);
      int kq  = idx % (BK / 4);
      float4 v = make_float4(0.f, 0.f, 0.f, 0.f);
      int m = m0 + row;
      if (m < M_NODES)
        v = *(const float4*)(in + (size_t)m * KTOT + kt + kq * 4);
      sA[kq * 4 + 0][row] = v.x; sA[kq * 4 + 1][row] = v.y;
      sA[kq * 4 + 2][row] = v.z; sA[kq * 4 + 3][row] = v.w;
    }
#pragma unroll
    for (int idx = tid; idx < BN * BK / 4; idx += NT) {
      int row = idx / (BK / 4);
      int kq  = idx % (BK / 4);
      float4 v = *(const float4*)(W + (size_t)(n0 + row) * KTOT + kt + kq * 4);
      sB[kq * 4 + 0][row] = v.x; sB[kq * 4 + 1][row] = v.y;
      sB[kq * 4 + 2][row] = v.z; sB[kq * 4 + 3][row] = v.w;
    }
    __syncthreads();
#pragma unroll
    for (int k = 0; k < BK; k++) {
      float4 a0 = *(const float4*)&sA[k][tm];
      float4 a1 = *(const float4*)&sA[k][tm + 4];
      ulonglong2 bl0 = *(const ulonglong2*)&sB[k][tn];
      ulonglong2 bl1 = *(const ulonglong2*)&sB[k][tn + 4];
      unsigned long long bp[4] = {bl0.x, bl0.y, bl1.x, bl1.y};
      float av[8] = {a0.x, a0.y, a0.z, a0.w, a1.x, a1.y, a1.z, a1.w};
#pragma unroll
      for (int i = 0; i < 8; i++) {
        unsigned long long ap = pack2(av[i]);
#pragma unroll
        for (int j = 0; j < 4; j++) acc[i][j] = ffma2(ap, bp[j], acc[i][j]);
      }
    }
    __syncthreads();
  }

  const int plane = (n0 + tn) / NOUT;
  const int col   = (n0 + tn) % NOUT;
  float* outp = (plane == 0) ? p0 : (plane == 1) ? p1 : (plane == 2) ? p2 : p3;
  float bv[8];
#pragma unroll
  for (int j = 0; j < 8; j++) bv[j] = (plane == 0) ? bias[col + j] : 0.0f;
#pragma unroll
  for (int i = 0; i < 8; i++) {
    int m = m0 + tm + i;
    if (m >= M_NODES) break;
    float2 r[4];
#pragma unroll
    for (int j = 0; j < 4; j++) {
      r[j] = *reinterpret_cast<float2*>(&acc[i][j]);
      r[j].x += bv[2 * j]; r[j].y += bv[2 * j + 1];
    }
    float4 w0 = make_float4(r[0].x, r[0].y, r[1].x, r[1].y);
    float4 w1 = make_float4(r[2].x, r[2].y, r[3].x, r[3].y);
    *(float4*)(outp + (size_t)m * NOUT + col)     = w0;
    *(float4*)(outp + (size_t)m * NOUT + col + 4) = w1;
  }
}

// ---------------- dropout (+ optional ELU first) ----------------
#if JAX_PARTITIONABLE
template <bool ELU>
__global__ void k_dropout(float* p, int n, unsigned k0, unsigned k1) {
  int i = blockIdx.x * blockDim.x + threadIdx.x;
  if (i >= n) return;
  unsigned o0, o1;
  threefry2x32(k0, k1, 0u, (unsigned)i, o0, o1);
  unsigned bits = o0 ^ o1;
  float u = __uint_as_float((bits >> 9) | 0x3F800000u) - 1.0f;
  float v = p[i];
  if (ELU) v = (v > 0.0f) ? v : expm1f(v);
  p[i] = (u < 0.5f) ? v * 2.0f : 0.0f;
}
#else
template <bool ELU>
__global__ void k_dropout(float* p, int n, unsigned k0, unsigned k1) {
  int j = blockIdx.x * blockDim.x + threadIdx.x;
  int half = n / 2;
  if (j >= half) return;
  unsigned o0, o1;
  threefry2x32(k0, k1, (unsigned)j, (unsigned)(j + half), o0, o1);
  float u0 = __uint_as_float((o0 >> 9) | 0x3F800000u) - 1.0f;
  float u1 = __uint_as_float((o1 >> 9) | 0x3F800000u) - 1.0f;
  float v0 = p[j], v1 = p[j + half];
  if (ELU) {
    v0 = (v0 > 0.0f) ? v0 : expm1f(v0);
    v1 = (v1 > 0.0f) ? v1 : expm1f(v1);
  }
  p[j]        = (u0 < 0.5f) ? v0 * 2.0f : 0.0f;
  p[j + half] = (u1 < 0.5f) ? v1 * 2.0f : 0.0f;
}
#endif

// ---------------- host orchestration ----------------
static inline int cdiv(long long a, int b) { return (int)((a + b - 1) / b); }

extern "C" void kernel_launch(void* const* d_in, const int* in_sizes, int n_in,
                              void* d_out, int out_size) {
  const float* x  = (const float*)d_in[0];
  const int*   ei = (const int*)d_in[1];   // int32 (JAX x64 disabled)
  const float* W1 = (const float*)d_in[2];
  const float* b1 = (const float*)d_in[3];
  const float* W2 = (const float*)d_in[4];
  const float* b2 = (const float*)d_in[5];
  const float* W3 = (const float*)d_in[6];
  const float* b3 = (const float*)d_in[7];
  float* out = (float*)d_out;

  int *deg, *fill, *rptr, *srcv, *bsum, *boff;
  float *dis, *wv, *bA, *bB, *bC, *bD, *bE;
  cudaGetSymbolAddress((void**)&deg,  g_deg);
  cudaGetSymbolAddress((void**)&fill, g_fill);
  cudaGetSymbolAddress((void**)&rptr, g_rptr);
  cudaGetSymbolAddress((void**)&bsum, g_bsum);
  cudaGetSymbolAddress((void**)&boff, g_boff);
  cudaGetSymbolAddress((void**)&srcv, g_src);
  cudaGetSymbolAddress((void**)&wv,   g_w);
  cudaGetSymbolAddress((void**)&dis,  g_dis);
  cudaGetSymbolAddress((void**)&bA,   g_bufA);
  cudaGetSymbolAddress((void**)&bB,   g_bufB);
  cudaGetSymbolAddress((void**)&bC,   g_bufC);
  cudaGetSymbolAddress((void**)&bD,   g_bufD);
  cudaGetSymbolAddress((void**)&bE,   g_bufE);

  unsigned dk1a, dk1b, dk2a, dk2b;
#if JAX_PARTITIONABLE
  threefry2x32(0u, 42u, 0u, 0u, dk1a, dk1b);
  threefry2x32(0u, 42u, 0u, 1u, dk2a, dk2b);
#else
  unsigned a0, a1, c0, c1;
  threefry2x32(0u, 42u, 0u, 2u, a0, c0);
  threefry2x32(0u, 42u, 1u, 3u, a1, c1);
  dk1a = a0; dk1b = a1; dk2a = c0; dk2b = c1;
#endif

  const int T = 256;
  const int GM = cdiv(M_NODES, 128);

  // ---- CSR build: deg -> (scan + dis) -> scatter(src, w) ----
  k_zero_i2<<<cdiv(M_NODES, T), T>>>(deg, fill, M_NODES);
  k_deg    <<<cdiv(N_EDG,   T), T>>>(ei, deg);
  k_scan1  <<<SCAN_B, 1024>>>(deg, rptr, bsum, dis);
  k_scan2  <<<1, 128>>>(bsum, boff);
  k_scan3  <<<SCAN_B, 1024>>>(rptr, boff);
  k_scatter<<<cdiv(N_EDG,   T), T>>>(ei, dis, rptr, fill, srcv, wv);

  // Horner per layer: P_k = h @ W_k^T; P2 += A P3; P1 += A P2; P0 += A P1.

  // ---- layer 1: 128 -> 128.  planes A(P0+b1), B, C, D.  h = x ----
  {
    const int N = 128;
    k_gemm4<128, 128, 16, 128, 128><<<dim3(GM, 4), 256>>>(bA, bB, bC, bD, x, W1, b1);
    const int NPB = 128 / (N / 4);
    k_spmm_csr<N><<<cdiv(M_NODES, NPB), 128>>>(bC, bD, rptr, srcv, wv);
    k_spmm_csr<N><<<cdiv(M_NODES, NPB), 128>>>(bB, bC, rptr, srcv, wv);
    k_spmm_csr<N><<<cdiv(M_NODES, NPB), 128>>>(bA, bB, rptr, srcv, wv);
    k_dropout<false><<<cdiv((long long)M_NODES * N, T), T>>>(bA, M_NODES * N, dk1a, dk1b);
  }

  // ---- layer 2: 128 -> 64.  planes B(P0+b2), C, D, E.  h = bA ----
  {
    const int N = 64;
    k_gemm4<128, 128, 16, 64, 128><<<dim3(GM, 2), 256>>>(bB, bC, bD, bE, bA, W2, b2);
    const int NPB = 128 / (N / 4);
    k_spmm_csr<N><<<cdiv(M_NODES, NPB), 128>>>(bD, bE, rptr, srcv, wv);
    k_spmm_csr<N><<<cdiv(M_NODES, NPB), 128>>>(bC, bD, rptr, srcv, wv);
    k_spmm_csr<N><<<cdiv(M_NODES, NPB), 128>>>(bB, bC, rptr, srcv, wv);
    k_dropout<true><<<cdiv((long long)M_NODES * N, T), T>>>(bB, M_NODES * N, dk2a, dk2b);
  }

  // ---- layer 3: 64 -> 16.  planes out(P0+b3), C, D, E.  h = bB ----
  {
    const int N = 16;
    k_gemm4<128, 64, 16, 16, 64><<<dim3(GM, 1), 128>>>(out, bC, bD, bE, bB, W3, b3);
    const int NPB = 128 / (N / 4);
    k_spmm_csr<N><<<cdiv(M_NODES, NPB), 128>>>(bD,  bE, rptr, srcv, wv);
    k_spmm_csr<N><<<cdiv(M_NODES, NPB), 128>>>(bC,  bD, rptr, srcv, wv);
    k_spmm_csr<N><<<cdiv(M_NODES, NPB), 128>>>(out, bC, rptr, srcv, wv);
  }
}

// round 14
// speedup vs baseline: 3.8139x; 1.1183x over previous
#include <cuda_runtime.h>
#include <cuda_bf16.h>
#include <cstdint>
#include <cstddef>

#define M_NODES 100000
#define N_EDG   1600000
#define JAX_PARTITIONABLE 1
#define SCAN_B 98   // ceil(M_NODES / 1024)

// ---------------- scratch (static device globals; no allocation) ----------------
__device__ int   g_deg[M_NODES];
__device__ int   g_fill[M_NODES];
__device__ int   g_rptr[M_NODES + 1];
__device__ int   g_bsum[SCAN_B];
__device__ int   g_boff[SCAN_B + 1];
__device__ int   g_src[N_EDG];
__device__ float g_w[N_EDG];
__device__ float g_dis[M_NODES];
__device__ __align__(16) float g_bufA[(size_t)M_NODES * 128];
__device__ __align__(16) float g_bufB[(size_t)M_NODES * 128];
__device__ __align__(16) float g_bufC[(size_t)M_NODES * 128];
__device__ __align__(16) float g_bufD[(size_t)M_NODES * 128];
__device__ __align__(16) float g_bufE[(size_t)M_NODES * 128];

// ---------------- threefry2x32 ----------------
__host__ __device__ __forceinline__ unsigned tf_rotl(unsigned x, int r) {
  return (x << r) | (x >> (32 - r));
}

__host__ __device__ __forceinline__ void threefry2x32(
    unsigned k0, unsigned k1, unsigned x0, unsigned x1,
    unsigned& o0, unsigned& o1) {
  unsigned ks2 = k0 ^ k1 ^ 0x1BD11BDAu;
  x0 += k0; x1 += k1;
#define TF_R(r) { x0 += x1; x1 = tf_rotl(x1, (r)); x1 ^= x0; }
  TF_R(13) TF_R(15) TF_R(26) TF_R(6)
  x0 += k1;  x1 += ks2 + 1u;
  TF_R(17) TF_R(29) TF_R(16) TF_R(24)
  x0 += ks2; x1 += k0 + 2u;
  TF_R(13) TF_R(15) TF_R(26) TF_R(6)
  x0 += k0;  x1 += k1 + 3u;
  TF_R(17) TF_R(29) TF_R(16) TF_R(24)
  x0 += k1;  x1 += ks2 + 4u;
  TF_R(13) TF_R(15) TF_R(26) TF_R(6)
  x0 += ks2; x1 += k0 + 5u;
#undef TF_R
  o0 = x0; o1 = x1;
}

// ---------------- warp-MMA helpers (baseline PTX, no 'a'-gated features) --------
__device__ __forceinline__ uint32_t smem_u32(const void* p) {
  uint32_t a;
  asm("{ .reg .u64 t; cvta.to.shared.u64 t, %1; cvt.u32.u64 %0, t; }"
      : "=r"(a) : "l"(p));
  return a;
}

__device__ __forceinline__ void ldsm_x4(uint32_t* r, uint32_t addr) {
  asm volatile("ldmatrix.sync.aligned.m8n8.x4.shared.b16 {%0,%1,%2,%3}, [%4];"
               : "=r"(r[0]), "=r"(r[1]), "=r"(r[2]), "=r"(r[3]) : "r"(addr));
}
__device__ __forceinline__ void ldsm_x2(uint32_t* r, uint32_t addr) {
  asm volatile("ldmatrix.sync.aligned.m8n8.x2.shared.b16 {%0,%1}, [%2];"
               : "=r"(r[0]), "=r"(r[1]) : "r"(addr));
}
__device__ __forceinline__ void mma16816(float* d, const uint32_t* a, const uint32_t* b) {
  asm volatile(
      "mma.sync.aligned.m16n8k16.row.col.f32.bf16.bf16.f32 "
      "{%0,%1,%2,%3}, {%4,%5,%6,%7}, {%8,%9}, {%0,%1,%2,%3};"
      : "+f"(d[0]), "+f"(d[1]), "+f"(d[2]), "+f"(d[3])
      : "r"(a[0]), "r"(a[1]), "r"(a[2]), "r"(a[3]), "r"(b[0]), "r"(b[1]));
}

__device__ __forceinline__ uint32_t pack_bf2(__nv_bfloat16 a, __nv_bfloat16 b) {
  __nv_bfloat162 v(a, b);
  return *reinterpret_cast<uint32_t*>(&v);
}

// ---------------- CSR build pipeline ----------------
__global__ void k_zero_i2(int* p, int* q, int n) {
  int i = blockIdx.x * blockDim.x + threadIdx.x;
  if (i < n) { p[i] = 0; q[i] = 0; }
}

__global__ void k_deg(const int* __restrict__ ei, int* __restrict__ deg) {
  int e = blockIdx.x * blockDim.x + threadIdx.x;
  if (e >= N_EDG) return;
  int col = ei[N_EDG + e];
  if ((unsigned)col < (unsigned)M_NODES) atomicAdd(&deg[col], 1);
}

__global__ void __launch_bounds__(1024)
k_scan1(const int* __restrict__ deg, int* __restrict__ rptr,
        int* __restrict__ bsum, float* __restrict__ dis) {
  __shared__ int sh[1024];
  int t = threadIdx.x;
  int idx = blockIdx.x * 1024 + t;
  int v = (idx < M_NODES) ? deg[idx] : 0;
  if (idx < M_NODES) dis[idx] = (v > 0) ? rsqrtf((float)v) : 0.0f;
  sh[t] = v;
  __syncthreads();
  int run = v;
  for (int off = 1; off < 1024; off <<= 1) {
    int u = (t >= off) ? sh[t - off] : 0;
    __syncthreads();
    run += u;
    sh[t] = run;
    __syncthreads();
  }
  if (idx < M_NODES) rptr[idx] = run - v;
  if (t == 1023) bsum[blockIdx.x] = run;
}

__global__ void __launch_bounds__(128)
k_scan2(const int* __restrict__ bsum, int* __restrict__ boff) {
  __shared__ int sh[SCAN_B];
  int t = threadIdx.x;
  if (t < SCAN_B) sh[t] = bsum[t];
  __syncthreads();
  if (t == 0) {
    int run = 0;
    for (int i = 0; i < SCAN_B; i++) {
      int v = sh[i];
      boff[i] = run;
      run += v;
    }
    boff[SCAN_B] = run;
  }
}

__global__ void __launch_bounds__(1024)
k_scan3(int* __restrict__ rptr, const int* __restrict__ boff) {
  int t = threadIdx.x;
  int idx = blockIdx.x * 1024 + t;
  if (idx < M_NODES) rptr[idx] += boff[blockIdx.x];
  if (idx == 0) rptr[M_NODES] = boff[SCAN_B];
}

__global__ void k_scatter(const int* __restrict__ ei, const float* __restrict__ dis,
                          const int* __restrict__ rptr, int* __restrict__ fill,
                          int* __restrict__ src, float* __restrict__ w) {
  int e = blockIdx.x * blockDim.x + threadIdx.x;
  if (e >= N_EDG) return;
  int row = ei[e];
  int col = ei[N_EDG + e];
  if ((unsigned)row >= (unsigned)M_NODES || (unsigned)col >= (unsigned)M_NODES) return;
  int pos = rptr[col] + atomicAdd(&fill[col], 1);
  src[pos] = row;
  w[pos] = dis[row] * dis[col];
}

// ---------------- CSR gather SpMM (unchanged winner) ----------------
template <int D>
__global__ void __launch_bounds__(128)
k_spmm_csr(float* __restrict__ out, const float* __restrict__ h,
           const int* __restrict__ rptr,
           const int* __restrict__ src,
           const float* __restrict__ w) {
  constexpr int TPN = D / 4;
  constexpr int NPB = 128 / TPN;
  int tid = threadIdx.x;
  int node = blockIdx.x * NPB + tid / TPN;
  if (node >= M_NODES) return;
  int c = (tid % TPN) * 4;
  int e0 = __ldg(&rptr[node]);
  int e1 = __ldg(&rptr[node + 1]);
  float4 acc = *(float4*)(out + (size_t)node * D + c);
  for (int e = e0; e < e1; e++) {
    int s = __ldg(&src[e]);
    float nm = __ldg(&w[e]);
    const float4 v = *(const float4*)(h + (size_t)s * D + c);
    acc.x = fmaf(nm, v.x, acc.x);
    acc.y = fmaf(nm, v.y, acc.y);
    acc.z = fmaf(nm, v.z, acc.z);
    acc.w = fmaf(nm, v.w, acc.w);
  }
  *(float4*)(out + (size_t)node * D + c) = acc;
}

// ---------------- tensor-core GEMM: 3xBF16 split via warp mma.sync ----------------
// CTA: 128x64 C-tile of C[M, NTOT] = in[M,KTOT] @ Wcat[NTOT,KTOT]^T.
// grid = (ceil(M/128), NTOT/64). 128 threads, 2x2 warp grid, warp tile 64x32.
// Whole K resident in smem: Ah/Al[128][KTOT(+8 pad)], Bh/Bl[64][KTOT+8] bf16.
// Accumulate Ah*Bh + Ah*Bl + Al*Bh in fp32 (3-product bf16 split, |err| ~ 2^-18).
template <int NOUT, int KTOT>
__global__ void __launch_bounds__(128)
k_gemm_mma(float* __restrict__ p0, float* __restrict__ p1,
           float* __restrict__ p2, float* __restrict__ p3,
           const float* __restrict__ in, const float* __restrict__ W,
           const float* __restrict__ bias) {
  extern __shared__ char smem[];
  constexpr int LDA = KTOT + 8;                   // bf16 elements per row (padded)
  constexpr size_t OFF_AH = 0;
  constexpr size_t OFF_AL = (size_t)128 * LDA * 2;
  constexpr size_t OFF_BH = 2 * OFF_AL;
  constexpr size_t OFF_BL = OFF_BH + (size_t)64 * LDA * 2;

  const int tid = threadIdx.x;
  const int lane = tid & 31, wid = tid >> 5;
  const int wm = (wid >> 1) * 64;                 // warp m-offset in tile
  const int wn = (wid & 1) * 32;                  // warp n-offset in tile
  const int m0 = blockIdx.x * 128;
  const int n0 = blockIdx.y * 64;

  // ---- A tile: fp32 -> hi/lo bf16, padded row-major ----
  for (int i = tid; i < (128 * KTOT) / 4; i += 128) {
    int row = (i * 4) / KTOT, k = (i * 4) % KTOT;
    int m = m0 + row;
    float4 a = (m < M_NODES) ? *(const float4*)(in + (size_t)m * KTOT + k)
                             : make_float4(0.f, 0.f, 0.f, 0.f);
    __nv_bfloat16 h0 = __float2bfloat16(a.x), h1 = __float2bfloat16(a.y);
    __nv_bfloat16 h2 = __float2bfloat16(a.z), h3 = __float2bfloat16(a.w);
    __nv_bfloat16 l0 = __float2bfloat16(a.x - __bfloat162float(h0));
    __nv_bfloat16 l1 = __float2bfloat16(a.y - __bfloat162float(h1));
    __nv_bfloat16 l2 = __float2bfloat16(a.z - __bfloat162float(h2));
    __nv_bfloat16 l3 = __float2bfloat16(a.w - __bfloat162float(h3));
    size_t off = ((size_t)row * LDA + k) * 2;
    *(uint32_t*)(smem + OFF_AH + off)     = pack_bf2(h0, h1);
    *(uint32_t*)(smem + OFF_AH + off + 4) = pack_bf2(h2, h3);
    *(uint32_t*)(smem + OFF_AL + off)     = pack_bf2(l0, l1);
    *(uint32_t*)(smem + OFF_AL + off + 4) = pack_bf2(l2, l3);
  }

  // ---- B tile: 64 rows of Wcat ----
  for (int i = tid; i < (64 * KTOT) / 4; i += 128) {
    int row = (i * 4) / KTOT, k = (i * 4) % KTOT;
    float4 a = *(const float4*)(W + (size_t)(n0 + row) * KTOT + k);
    __nv_bfloat16 h0 = __float2bfloat16(a.x), h1 = __float2bfloat16(a.y);
    __nv_bfloat16 h2 = __float2bfloat16(a.z), h3 = __float2bfloat16(a.w);
    __nv_bfloat16 l0 = __float2bfloat16(a.x - __bfloat162float(h0));
    __nv_bfloat16 l1 = __float2bfloat16(a.y - __bfloat162float(h1));
    __nv_bfloat16 l2 = __float2bfloat16(a.z - __bfloat162float(h2));
    __nv_bfloat16 l3 = __float2bfloat16(a.w - __bfloat162float(h3));
    size_t off = ((size_t)row * LDA + k) * 2;
    *(uint32_t*)(smem + OFF_BH + off)     = pack_bf2(h0, h1);
    *(uint32_t*)(smem + OFF_BH + off + 4) = pack_bf2(h2, h3);
    *(uint32_t*)(smem + OFF_BL + off)     = pack_bf2(l0, l1);
    *(uint32_t*)(smem + OFF_BL + off + 4) = pack_bf2(l2, l3);
  }
  __syncthreads();

  const uint32_t sb = smem_u32(smem);
  float acc[4][4][4];
#pragma unroll
  for (int mt = 0; mt < 4; mt++)
#pragma unroll
    for (int nt = 0; nt < 4; nt++)
#pragma unroll
      for (int f = 0; f < 4; f++) acc[mt][nt][f] = 0.0f;

  // ldmatrix lane-address components
  const int arow = wm + (lane & 15);
  const int acol = (lane >> 4) * 8;
  const int brow = wn + (lane & 7);
  const int bcol = ((lane >> 3) & 1) * 8;

  for (int k0 = 0; k0 < KTOT; k0 += 16) {
    uint32_t Ah[4][4], Al[4][4], Bh[4][2], Bl[4][2];
#pragma unroll
    for (int mt = 0; mt < 4; mt++) {
      uint32_t off = (uint32_t)(((arow + mt * 16) * LDA + k0 + acol) * 2);
      ldsm_x4(Ah[mt], sb + (uint32_t)OFF_AH + off);
      ldsm_x4(Al[mt], sb + (uint32_t)OFF_AL + off);
    }
#pragma unroll
    for (int nt = 0; nt < 4; nt++) {
      uint32_t off = (uint32_t)(((brow + nt * 8) * LDA + k0 + bcol) * 2);
      ldsm_x2(Bh[nt], sb + (uint32_t)OFF_BH + off);
      ldsm_x2(Bl[nt], sb + (uint32_t)OFF_BL + off);
    }
#pragma unroll
    for (int mt = 0; mt < 4; mt++)
#pragma unroll
      for (int nt = 0; nt < 4; nt++) {
        mma16816(acc[mt][nt], Ah[mt], Bh[nt]);
        mma16816(acc[mt][nt], Ah[mt], Bl[nt]);
        mma16816(acc[mt][nt], Al[mt], Bh[nt]);
      }
  }

  // ---- epilogue: fragment (c0,c1)=row t/4, cols 2(t%4); (c2,c3)=row+8 ----
#pragma unroll
  for (int mt = 0; mt < 4; mt++) {
    int gm0 = m0 + wm + mt * 16 + (lane >> 2);
#pragma unroll
    for (int nt = 0; nt < 4; nt++) {
      int gc = n0 + wn + nt * 8 + 2 * (lane & 3);
      int plane = gc / NOUT;
      int pc = gc % NOUT;
      float* op = (plane == 0) ? p0 : (plane == 1) ? p1 : (plane == 2) ? p2 : p3;
      float bx = 0.f, by = 0.f;
      if (plane == 0) { bx = bias[pc]; by = bias[pc + 1]; }
      if (gm0 < M_NODES) {
        float2 v0 = make_float2(acc[mt][nt][0] + bx, acc[mt][nt][1] + by);
        *(float2*)(op + (size_t)gm0 * NOUT + pc) = v0;
      }
      if (gm0 + 8 < M_NODES) {
        float2 v1 = make_float2(acc[mt][nt][2] + bx, acc[mt][nt][3] + by);
        *(float2*)(op + (size_t)(gm0 + 8) * NOUT + pc) = v1;
      }
    }
  }
}

// ---------------- dropout (+ optional ELU first) ----------------
#if JAX_PARTITIONABLE
template <bool ELU>
__global__ void k_dropout(float* p, int n, unsigned k0, unsigned k1) {
  int i = blockIdx.x * blockDim.x + threadIdx.x;
  if (i >= n) return;
  unsigned o0, o1;
  threefry2x32(k0, k1, 0u, (unsigned)i, o0, o1);
  unsigned bits = o0 ^ o1;
  float u = __uint_as_float((bits >> 9) | 0x3F800000u) - 1.0f;
  float v = p[i];
  if (ELU) v = (v > 0.0f) ? v : expm1f(v);
  p[i] = (u < 0.5f) ? v * 2.0f : 0.0f;
}
#else
template <bool ELU>
__global__ void k_dropout(float* p, int n, unsigned k0, unsigned k1) {
  int j = blockIdx.x * blockDim.x + threadIdx.x;
  int half = n / 2;
  if (j >= half) return;
  unsigned o0, o1;
  threefry2x32(k0, k1, (unsigned)j, (unsigned)(j + half), o0, o1);
  float u0 = __uint_as_float((o0 >> 9) | 0x3F800000u) - 1.0f;
  float u1 = __uint_as_float((o1 >> 9) | 0x3F800000u) - 1.0f;
  float v0 = p[j], v1 = p[j + half];
  if (ELU) {
    v0 = (v0 > 0.0f) ? v0 : expm1f(v0);
    v1 = (v1 > 0.0f) ? v1 : expm1f(v1);
  }
  p[j]        = (u0 < 0.5f) ? v0 * 2.0f : 0.0f;
  p[j + half] = (u1 < 0.5f) ? v1 * 2.0f : 0.0f;
}
#endif

// ---------------- host orchestration ----------------
static inline int cdiv(long long a, int b) { return (int)((a + b - 1) / b); }

extern "C" void kernel_launch(void* const* d_in, const int* in_sizes, int n_in,
                              void* d_out, int out_size) {
  const float* x  = (const float*)d_in[0];
  const int*   ei = (const int*)d_in[1];   // int32 (JAX x64 disabled)
  const float* W1 = (const float*)d_in[2];
  const float* b1 = (const float*)d_in[3];
  const float* W2 = (const float*)d_in[4];
  const float* b2 = (const float*)d_in[5];
  const float* W3 = (const float*)d_in[6];
  const float* b3 = (const float*)d_in[7];
  float* out = (float*)d_out;

  int *deg, *fill, *rptr, *srcv, *bsum, *boff;
  float *dis, *wv, *bA, *bB, *bC, *bD, *bE;
  cudaGetSymbolAddress((void**)&deg,  g_deg);
  cudaGetSymbolAddress((void**)&fill, g_fill);
  cudaGetSymbolAddress((void**)&rptr, g_rptr);
  cudaGetSymbolAddress((void**)&bsum, g_bsum);
  cudaGetSymbolAddress((void**)&boff, g_boff);
  cudaGetSymbolAddress((void**)&srcv, g_src);
  cudaGetSymbolAddress((void**)&wv,   g_w);
  cudaGetSymbolAddress((void**)&dis,  g_dis);
  cudaGetSymbolAddress((void**)&bA,   g_bufA);
  cudaGetSymbolAddress((void**)&bB,   g_bufB);
  cudaGetSymbolAddress((void**)&bC,   g_bufC);
  cudaGetSymbolAddress((void**)&bD,   g_bufD);
  cudaGetSymbolAddress((void**)&bE,   g_bufE);

  unsigned dk1a, dk1b, dk2a, dk2b;
#if JAX_PARTITIONABLE
  threefry2x32(0u, 42u, 0u, 0u, dk1a, dk1b);
  threefry2x32(0u, 42u, 0u, 1u, dk2a, dk2b);
#else
  unsigned a0, a1, c0, c1;
  threefry2x32(0u, 42u, 0u, 2u, a0, c0);
  threefry2x32(0u, 42u, 1u, 3u, a1, c1);
  dk1a = a0; dk1b = a1; dk2a = c0; dk2b = c1;
#endif

  const int T = 256;
  const int GM = cdiv(M_NODES, 128);   // 782

  // dynamic smem: (2*128 + 2*64) rows * (KTOT+8) bf16
  const int SM12 = 384 * (128 + 8) * 2;  // 104448 for KTOT=128
  const int SM3  = 384 * (64 + 8) * 2;   // 55296 for KTOT=64
  cudaFuncSetAttribute(k_gemm_mma<128, 128>, cudaFuncAttributeMaxDynamicSharedMemorySize, SM12);
  cudaFuncSetAttribute(k_gemm_mma<64, 128>,  cudaFuncAttributeMaxDynamicSharedMemorySize, SM12);
  cudaFuncSetAttribute(k_gemm_mma<16, 64>,   cudaFuncAttributeMaxDynamicSharedMemorySize, SM3);

  // ---- CSR build: deg -> (scan + dis) -> scatter(src, w) ----
  k_zero_i2<<<cdiv(M_NODES, T), T>>>(deg, fill, M_NODES);
  k_deg    <<<cdiv(N_EDG,   T), T>>>(ei, deg);
  k_scan1  <<<SCAN_B, 1024>>>(deg, rptr, bsum, dis);
  k_scan2  <<<1, 128>>>(bsum, boff);
  k_scan3  <<<SCAN_B, 1024>>>(rptr, boff);
  k_scatter<<<cdiv(N_EDG,   T), T>>>(ei, dis, rptr, fill, srcv, wv);

  // Horner per layer: P_k = h @ W_k^T; P2 += A P3; P1 += A P2; P0 += A P1.

  // ---- layer 1: 128 -> 128.  planes A(P0+b1), B, C, D.  h = x ----
  {
    const int N = 128;
    k_gemm_mma<128, 128><<<dim3(GM, 8), 128, SM12>>>(bA, bB, bC, bD, x, W1, b1);
    const int NPB = 128 / (N / 4);
    k_spmm_csr<N><<<cdiv(M_NODES, NPB), 128>>>(bC, bD, rptr, srcv, wv);
    k_spmm_csr<N><<<cdiv(M_NODES, NPB), 128>>>(bB, bC, rptr, srcv, wv);
    k_spmm_csr<N><<<cdiv(M_NODES, NPB), 128>>>(bA, bB, rptr, srcv, wv);
    k_dropout<false><<<cdiv((long long)M_NODES * N, T), T>>>(bA, M_NODES * N, dk1a, dk1b);
  }

  // ---- layer 2: 128 -> 64.  planes B(P0+b2), C, D, E.  h = bA ----
  {
    const int N = 64;
    k_gemm_mma<64, 128><<<dim3(GM, 4), 128, SM12>>>(bB, bC, bD, bE, bA, W2, b2);
    const int NPB = 128 / (N / 4);
    k_spmm_csr<N><<<cdiv(M_NODES, NPB), 128>>>(bD, bE, rptr, srcv, wv);
    k_spmm_csr<N><<<cdiv(M_NODES, NPB), 128>>>(bC, bD, rptr, srcv, wv);
    k_spmm_csr<N><<<cdiv(M_NODES, NPB), 128>>>(bB, bC, rptr, srcv, wv);
    k_dropout<true><<<cdiv((long long)M_NODES * N, T), T>>>(bB, M_NODES * N, dk2a, dk2b);
  }

  // ---- layer 3: 64 -> 16.  planes out(P0+b3), C, D, E.  h = bB ----
  {
    const int N = 16;
    k_gemm_mma<16, 64><<<dim3(GM, 1), 128, SM3>>>(out, bC, bD, bE, bB, W3, b3);
    const int NPB = 128 / (N / 4);
    k_spmm_csr<N><<<cdiv(M_NODES, NPB), 128>>>(bD,  bE, rptr, srcv, wv);
    k_spmm_csr<N><<<cdiv(M_NODES, NPB), 128>>>(bC,  bD, rptr, srcv, wv);
    k_spmm_csr<N><<<cdiv(M_NODES, NPB), 128>>>(out, bC, rptr, srcv, wv);
  }
}